// round 8
// baseline (speedup 1.0000x reference)
#include <cuda_runtime.h>
#include <cuda_bf16.h>
#include <cuda.h>
#include <math.h>
#include <cstdint>

// Problem constants
#define BATCH 4
#define TLEN 2048
#define DMODEL 2048
#define DHALF 1024
#define NROWS (BATCH * TLEN)          // 8192
#define KGIST 16
#define NHEADS 16
#define HDIM 128
#define KUP 1025                       // gist_up feature dim (dh + 1)
#define MAXPART 32

// ------------------------- scratch (device globals; no allocation) ---------
__device__ float g_y [NROWS * DMODEL];
__device__ float g_u [NROWS * DMODEL];
__device__ float g_x1[NROWS * DMODEL];
__device__ float g_x2[NROWS * DMODEL];
__device__ float g_q [NROWS * DMODEL];
__device__ __nv_bfloat16 g_ahi[NROWS * DMODEL];
__device__ __nv_bfloat16 g_alo[NROWS * DMODEL];
__device__ __nv_bfloat16 g_whi[DMODEL * DMODEL];
__device__ __nv_bfloat16 g_wlo[DMODEL * DMODEL];
__device__ float g_feat[BATCH * KGIST * KUP];
__device__ float g_part[MAXPART * BATCH * KGIST * DMODEL];   // split-K partials
__device__ float g_repr[BATCH * KGIST * DMODEL];
__device__ float g_kh  [BATCH * KGIST * DMODEL];
__device__ float g_v   [BATCH * KGIST * DMODEL];
__device__ float g_shc[4 * DHALF];
__device__ float g_shs[4 * DHALF];
__device__ float g_gc [BATCH * DHALF];
__device__ float g_gs [BATCH * DHALF];

// ------------------------- helpers -----------------------------------------
__device__ __forceinline__ uint32_t smem_u32(const void* p) {
    uint32_t a;
    asm("{ .reg .u64 t; cvta.to.shared.u64 t, %1; cvt.u32.u64 %0, t; }" : "=r"(a) : "l"(p));
    return a;
}

__device__ __forceinline__ void cpasync16(uint32_t dst, const void* src) {
    asm volatile("cp.async.cg.shared.global [%0], [%1], 16;" :: "r"(dst), "l"(src));
}
#define CP_COMMIT() asm volatile("cp.async.commit_group;" ::: "memory")
#define CP_WAIT(n)  asm volatile("cp.async.wait_group %0;" :: "n"(n) : "memory")

__device__ __forceinline__ float block_reduce_sum256(float v) {
    __shared__ float sb[8];
    int lane = threadIdx.x & 31, wid = threadIdx.x >> 5;
    #pragma unroll
    for (int o = 16; o > 0; o >>= 1) v += __shfl_xor_sync(0xffffffffu, v, o);
    if (lane == 0) sb[wid] = v;
    __syncthreads();
    float r = 0.f;
    #pragma unroll
    for (int i = 0; i < 8; i++) r += sb[i];
    __syncthreads();
    return r;
}

__device__ __forceinline__ void split_hi_lo(float v, __nv_bfloat16& h, __nv_bfloat16& l) {
    h = __float2bfloat16(v);
    l = __float2bfloat16(v - __bfloat162float(h));
}

__device__ __forceinline__ void mma16816(float* d, const uint32_t* a, uint32_t b0, uint32_t b1) {
    asm volatile(
        "mma.sync.aligned.m16n8k16.row.col.f32.bf16.bf16.f32 "
        "{%0,%1,%2,%3}, {%4,%5,%6,%7}, {%8,%9}, {%0,%1,%2,%3};"
        : "+f"(d[0]), "+f"(d[1]), "+f"(d[2]), "+f"(d[3])
        : "r"(a[0]), "r"(a[1]), "r"(a[2]), "r"(a[3]), "r"(b0), "r"(b1));
}

__device__ __forceinline__ void ldsm_x4(uint32_t* r, uint32_t addr) {
    asm volatile("ldmatrix.sync.aligned.m8n8.x4.shared.b16 {%0,%1,%2,%3}, [%4];"
                 : "=r"(r[0]), "=r"(r[1]), "=r"(r[2]), "=r"(r[3]) : "r"(addr));
}

// ------------------------- small prep kernels -------------------------------
__global__ void prep_sheaf_cs_kernel(const float* __restrict__ thetas,
                                     float* __restrict__ c, float* __restrict__ s) {
    int i = blockIdx.x * 256 + threadIdx.x;
    if (i < 4 * DHALF) { float th = thetas[i]; c[i] = cosf(th); s[i] = sinf(th); }
}

__global__ void gist_theta_kernel(const float* __restrict__ gtheta,
                                  const float* __restrict__ gmag,
                                  const float* __restrict__ gw,
                                  const float* __restrict__ gstrength,
                                  float* __restrict__ gc, float* __restrict__ gs) {
    int b = blockIdx.x;
    float wk[KGIST]; float wsum = 0.f;
    #pragma unroll
    for (int k = 0; k < KGIST; k++) { wk[k] = gw[b * KGIST + k] * gmag[b * KGIST + k]; wsum += wk[k]; }
    float inv = 1.f / (wsum + 1e-8f);
    float sig = 1.f / (1.f + expf(-gstrength[0]));
    for (int p = threadIdx.x; p < DHALF; p += 256) {
        float th = 0.f;
        #pragma unroll
        for (int k = 0; k < KGIST; k++) th += (wk[k] * inv) * gtheta[(size_t)(b * KGIST + k) * DHALF + p];
        th *= sig;
        gc[b * DHALF + p] = cosf(th);
        gs[b * DHALF + p] = sinf(th);
    }
}

__global__ void feat_kernel(const float* __restrict__ gtheta,
                            const float* __restrict__ gmag,
                            float* __restrict__ feat) {
    int r = blockIdx.x;           // 0..63
    for (int f = threadIdx.x; f < KUP; f += 256) {
        float v = (f < DHALF) ? gtheta[(size_t)r * DHALF + f] : gmag[r];
        feat[(size_t)r * KUP + f] = v;
    }
}

// fp32 -> bf16 hi/lo splitter (weights)
__global__ void split_kernel(const float* __restrict__ in,
                             __nv_bfloat16* __restrict__ hi,
                             __nv_bfloat16* __restrict__ lo, int n4) {
    int i = blockIdx.x * 256 + threadIdx.x;
    if (i >= n4) return;
    float4 v = ((const float4*)in)[i];
    __nv_bfloat16 h0, h1, h2, h3, l0, l1, l2, l3;
    split_hi_lo(v.x, h0, l0); split_hi_lo(v.y, h1, l1);
    split_hi_lo(v.z, h2, l2); split_hi_lo(v.w, h3, l3);
    ((__nv_bfloat162*)hi)[2 * i]     = __nv_bfloat162(h0, h1);
    ((__nv_bfloat162*)hi)[2 * i + 1] = __nv_bfloat162(h2, h3);
    ((__nv_bfloat162*)lo)[2 * i]     = __nv_bfloat162(l0, l1);
    ((__nv_bfloat162*)lo)[2 * i + 1] = __nv_bfloat162(l2, l3);
}

// ------------------------- LayerNorm (optionally emits bf16 hi/lo) ---------
__global__ void ln_kernel(const float* __restrict__ in,
                          const float* __restrict__ w,
                          const float* __restrict__ b,
                          float* __restrict__ outf,
                          __nv_bfloat16* __restrict__ outh,
                          __nv_bfloat16* __restrict__ outl) {
    int row = blockIdx.x;
    const float* p = in + (size_t)row * DMODEL;
    float v[8];
    #pragma unroll
    for (int j = 0; j < 8; j++) v[j] = p[threadIdx.x + 256 * j];
    float s = 0.f;
    #pragma unroll
    for (int j = 0; j < 8; j++) s += v[j];
    float mean = block_reduce_sum256(s) * (1.f / DMODEL);
    float q = 0.f;
    #pragma unroll
    for (int j = 0; j < 8; j++) { float d = v[j] - mean; q += d * d; }
    float var = block_reduce_sum256(q) * (1.f / DMODEL);
    float rstd = rsqrtf(var + 1e-5f);
    #pragma unroll
    for (int j = 0; j < 8; j++) {
        int i = threadIdx.x + 256 * j;
        float val = (v[j] - mean) * rstd * w[i] + b[i];
        size_t idx = (size_t)row * DMODEL + i;
        if (outf) outf[idx] = val;
        if (outh) {
            __nv_bfloat16 h, l; split_hi_lo(val, h, l);
            outh[idx] = h; outl[idx] = l;
        }
    }
}

// ------------------------- sheaf (writes fp32 u + bf16 hi/lo) --------------
__global__ void sheaf_kernel(const float* __restrict__ y,
                             const float* __restrict__ ctab,
                             const float* __restrict__ stab,
                             const float* __restrict__ alpha_p,
                             float* __restrict__ u,
                             __nv_bfloat16* __restrict__ uh,
                             __nv_bfloat16* __restrict__ ul) {
    int row = blockIdx.x;
    int t = row & (TLEN - 1);
    float a = fabsf(alpha_p[0]);
    const float* yr = y + (size_t)row * DMODEL;
    #pragma unroll
    for (int jj = 0; jj < 4; jj++) {
        int p = threadIdx.x + 256 * jj;
        float r0 = yr[p], i0 = yr[p + DHALF];
        float lr = 4.f * r0, li = 4.f * i0;
        #pragma unroll
        for (int idx = 0; idx < 4; idx++) {
            int delta = idx - 3;
            float rs, is;
            if (delta == 0) { rs = r0; is = i0; }
            else if (t + delta >= 0) {
                const float* ys = y + (size_t)(row + delta) * DMODEL;
                rs = ys[p]; is = ys[p + DHALF];
            } else { rs = 0.f; is = 0.f; }
            float c = ctab[idx * DHALF + p], s = stab[idx * DHALF + p];
            lr -= c * rs + s * is;
            li -= c * is - s * rs;
        }
        float outr = r0 - a * lr, outi = i0 - a * li;
        size_t br = (size_t)row * DMODEL + p, bi = br + DHALF;
        u[br] = outr; u[bi] = outi;
        __nv_bfloat16 h, l;
        split_hi_lo(outr, h, l); uh[br] = h; ul[br] = l;
        split_hi_lo(outi, h, l); uh[bi] = h; ul[bi] = l;
    }
}

// ------------------------- fused gist rotation block ------------------------
__global__ void gist_rot_kernel(const float* __restrict__ x1,
                                const float* __restrict__ lw, const float* __restrict__ lb,
                                const float* __restrict__ grw, const float* __restrict__ grb,
                                const float* __restrict__ gc, const float* __restrict__ gs,
                                float* __restrict__ x2) {
    int row = blockIdx.x;
    int b = row >> 11;
    const float* p = x1 + (size_t)row * DMODEL;
    float xr[4], xi[4];
    #pragma unroll
    for (int jj = 0; jj < 4; jj++) {
        int q = threadIdx.x + 256 * jj;
        xr[jj] = p[q]; xi[jj] = p[q + DHALF];
    }
    float s1 = 0.f;
    #pragma unroll
    for (int jj = 0; jj < 4; jj++) s1 += xr[jj] + xi[jj];
    float m1 = block_reduce_sum256(s1) * (1.f / DMODEL);
    float q1 = 0.f;
    #pragma unroll
    for (int jj = 0; jj < 4; jj++) {
        float dr = xr[jj] - m1, di = xi[jj] - m1;
        q1 += dr * dr + di * di;
    }
    float rstd1 = rsqrtf(block_reduce_sum256(q1) * (1.f / DMODEL) + 1e-5f);

    float xnr[4], xni[4], rr[4], ri[4];
    #pragma unroll
    for (int jj = 0; jj < 4; jj++) {
        int q = threadIdx.x + 256 * jj;
        xnr[jj] = (xr[jj] - m1) * rstd1 * lw[q] + lb[q];
        xni[jj] = (xi[jj] - m1) * rstd1 * lw[q + DHALF] + lb[q + DHALF];
        float c = gc[b * DHALF + q], sn = gs[b * DHALF + q];
        rr[jj] = xnr[jj] * c - xni[jj] * sn;
        ri[jj] = xnr[jj] * sn + xni[jj] * c;
    }
    float s2 = 0.f;
    #pragma unroll
    for (int jj = 0; jj < 4; jj++) s2 += rr[jj] + ri[jj];
    float m2 = block_reduce_sum256(s2) * (1.f / DMODEL);
    float q2 = 0.f;
    #pragma unroll
    for (int jj = 0; jj < 4; jj++) {
        float dr = rr[jj] - m2, di = ri[jj] - m2;
        q2 += dr * dr + di * di;
    }
    float rstd2 = rsqrtf(block_reduce_sum256(q2) * (1.f / DMODEL) + 1e-5f);

    #pragma unroll
    for (int jj = 0; jj < 4; jj++) {
        int q = threadIdx.x + 256 * jj;
        float outr = xr[jj] + (rr[jj] - m2) * rstd2 * grw[q] + grb[q] - xnr[jj];
        float outi = xi[jj] + (ri[jj] - m2) * rstd2 * grw[q + DHALF] + grb[q + DHALF] - xni[jj];
        x2[(size_t)row * DMODEL + q]         = outr;
        x2[(size_t)row * DMODEL + q + DHALF] = outi;
    }
}

// ------------------- split-K small GEMM (M=64, N=2048) ----------------------
#define SKC 64
__global__ __launch_bounds__(256, 4)
void smallgemm_kernel(const float* __restrict__ A, int lda,
                      const float* __restrict__ W, int ldw,
                      float* __restrict__ part, int Kdim) {
    __shared__ float Fs[64][SKC + 1];
    __shared__ float Ws[64][SKC + 1];
    const int n0 = blockIdx.x * 64;
    const int k0 = blockIdx.y * SKC;
    const int tid = threadIdx.x;

    for (int idx = tid; idx < 64 * SKC; idx += 256) {
        int r = idx >> 6, c = idx & 63;
        int k = k0 + c;
        Fs[r][c] = (k < Kdim) ? A[(size_t)r * lda + k] : 0.f;
        Ws[r][c] = (k < Kdim) ? W[(size_t)(n0 + r) * ldw + k] : 0.f;
    }
    __syncthreads();

    const int tx = tid & 15, ty = tid >> 4;
    float acc[4][4];
    #pragma unroll
    for (int i = 0; i < 4; i++)
        #pragma unroll
        for (int j = 0; j < 4; j++) acc[i][j] = 0.f;

    for (int k = 0; k < SKC; k++) {
        float ra[4], rb[4];
        #pragma unroll
        for (int i = 0; i < 4; i++) ra[i] = Fs[ty * 4 + i][k];
        #pragma unroll
        for (int j = 0; j < 4; j++) rb[j] = Ws[tx * 4 + j][k];
        #pragma unroll
        for (int i = 0; i < 4; i++)
            #pragma unroll
            for (int j = 0; j < 4; j++) acc[i][j] += ra[i] * rb[j];
    }

    float* pz = part + (size_t)blockIdx.y * (64 * DMODEL);
    #pragma unroll
    for (int i = 0; i < 4; i++)
        #pragma unroll
        for (int j = 0; j < 4; j++)
            pz[(size_t)(ty * 4 + i) * DMODEL + n0 + tx * 4 + j] = acc[i][j];
}

__global__ void skreduce_kernel(const float* __restrict__ part, int nparts,
                                const float* __restrict__ bias,
                                float* __restrict__ out) {
    int idx = blockIdx.x * 256 + threadIdx.x;
    if (idx >= 64 * DMODEL) return;
    float s = bias ? bias[idx & (DMODEL - 1)] : 0.f;
    for (int z = 0; z < nparts; z++) s += part[(size_t)z * (64 * DMODEL) + idx];
    out[idx] = s;
}

// ------------------------- bf16 HMMA 3-term GEMM ----------------------------
// CTA tile 128x256, BK=64, 8 warps as 2m x 4n, warp tile 64x64, ldmatrix loads.
#define GBK 64
#define ROWP 72
// stage layout (bf16 elements): Ahi[128*72] Alo[128*72] Whi[256*72] Wlo[256*72]
#define OFF_ALO   (128 * ROWP)                 // 9216
#define OFF_W     (256 * ROWP)                 // 18432  (byte off = *2)
#define OFF_WLO   (OFF_W + 256 * ROWP)         // 36864
#define STAGE_EL  (768 * ROWP)                 // 55296 elements
#define STAGE_B   (STAGE_EL * 2)               // 110592 bytes
#define SMEM_GEMM (2 * STAGE_B)                // 221184 bytes

__global__ __launch_bounds__(256, 1)
void gemm_bf16_kernel(const __nv_bfloat16* __restrict__ Ahi,
                      const __nv_bfloat16* __restrict__ Alo,
                      const __nv_bfloat16* __restrict__ Whi,
                      const __nv_bfloat16* __restrict__ Wlo,
                      float* __restrict__ D,
                      const float* __restrict__ add1,
                      const float* __restrict__ add2) {
    extern __shared__ __nv_bfloat16 sm[];
    const int tid  = threadIdx.x;
    const int lane = tid & 31;
    const int warp = tid >> 5;
    const int wm = warp & 1;            // 2 m-tiles of 64
    const int wn = warp >> 1;           // 4 n-tiles of 64
    const int m0 = blockIdx.y * 128, n0 = blockIdx.x * 256;
    const uint32_t smb = smem_u32(sm);

    float acc[4][8][4];
    #pragma unroll
    for (int mt = 0; mt < 4; mt++)
        #pragma unroll
        for (int nt = 0; nt < 8; nt++)
            #pragma unroll
            for (int j = 0; j < 4; j++) acc[mt][nt][j] = 0.f;

    const int NCHUNK = DMODEL / GBK;    // 32

    // per-lane ldmatrix address components
    const int a_row = lane & 15;
    const int a_k8  = (lane >= 16) ? 8 : 0;
    const int b_row = (lane & 7) + ((lane >= 16) ? 8 : 0);
    const int b_k8  = ((lane >> 3) & 1) ? 8 : 0;

    // stage loader: A rows 0..255 (hi then lo), W rows 0..511 (hi then lo)
    auto issue_stage = [&](int kc, uint32_t sbase) {
        const int k0 = kc * GBK;
        #pragma unroll
        for (int i = 0; i < 8; i++) {                  // A: 2048 cp16
            int idx = tid + i * 256;
            int row = idx >> 3, ch = idx & 7;          // row 0..255
            const __nv_bfloat16* src = (row < 128)
                ? Ahi + (size_t)(m0 + row) * DMODEL + k0 + ch * 8
                : Alo + (size_t)(m0 + row - 128) * DMODEL + k0 + ch * 8;
            cpasync16(sbase + (uint32_t)(row * ROWP + ch * 8) * 2, src);
        }
        #pragma unroll
        for (int i = 0; i < 16; i++) {                 // W: 4096 cp16
            int idx = tid + i * 256;
            int row = idx >> 3, ch = idx & 7;          // row 0..511
            const __nv_bfloat16* src = (row < 256)
                ? Whi + (size_t)(n0 + row) * DMODEL + k0 + ch * 8
                : Wlo + (size_t)(n0 + row - 256) * DMODEL + k0 + ch * 8;
            cpasync16(sbase + (uint32_t)(OFF_W + row * ROWP + ch * 8) * 2, src);
        }
    };

    issue_stage(0, smb);
    CP_COMMIT();

    for (int kc = 0; kc < NCHUNK; kc++) {
        if (kc + 1 < NCHUNK) {
            issue_stage(kc + 1, smb + ((kc + 1) & 1) * STAGE_B);
            CP_COMMIT();
            CP_WAIT(1);
        } else {
            CP_WAIT(0);
        }
        __syncthreads();

        const uint32_t sbase = smb + (kc & 1) * STAGE_B;

        #pragma unroll
        for (int ks = 0; ks < 4; ks++) {
            const int kb = ks * 16;
            // A fragments: 4 m-units x (hi, lo)
            uint32_t ah[4][4], al[4][4];
            #pragma unroll
            for (int mt = 0; mt < 4; mt++) {
                int rowe = (wm * 64 + mt * 16 + a_row) * ROWP + kb + a_k8;
                ldsm_x4(ah[mt], sbase + (uint32_t)rowe * 2);
                ldsm_x4(al[mt], sbase + (uint32_t)(rowe + OFF_ALO) * 2);
            }
            // B fragments: 4 pairs of n-units
            #pragma unroll
            for (int ntp = 0; ntp < 4; ntp++) {
                uint32_t bh[4], bl[4];
                int rowe = OFF_W + (wn * 64 + ntp * 16 + b_row) * ROWP + kb + b_k8;
                ldsm_x4(bh, sbase + (uint32_t)rowe * 2);
                ldsm_x4(bl, sbase + (uint32_t)(rowe + OFF_W) * 2);
                #pragma unroll
                for (int mt = 0; mt < 4; mt++) {
                    mma16816(acc[mt][2 * ntp],     ah[mt], bh[0], bh[1]);
                    mma16816(acc[mt][2 * ntp],     ah[mt], bl[0], bl[1]);
                    mma16816(acc[mt][2 * ntp],     al[mt], bh[0], bh[1]);
                    mma16816(acc[mt][2 * ntp + 1], ah[mt], bh[2], bh[3]);
                    mma16816(acc[mt][2 * ntp + 1], ah[mt], bl[2], bl[3]);
                    mma16816(acc[mt][2 * ntp + 1], al[mt], bh[2], bh[3]);
                }
            }
        }
        __syncthreads();
    }

    // epilogue
    const int r  = lane >> 2;
    const int c2 = lane & 3;
    #pragma unroll
    for (int mt = 0; mt < 4; mt++) {
        #pragma unroll
        for (int nt = 0; nt < 8; nt++) {
            int row0 = m0 + wm * 64 + mt * 16 + r;
            int col  = n0 + wn * 64 + nt * 8 + c2 * 2;
            size_t i0 = (size_t)row0 * DMODEL + col;
            size_t i1 = i0 + (size_t)8 * DMODEL;
            float2 v0 = make_float2(acc[mt][nt][0], acc[mt][nt][1]);
            float2 v1 = make_float2(acc[mt][nt][2], acc[mt][nt][3]);
            if (add1) {
                float2 a0 = *(const float2*)(add1 + i0);
                float2 a1 = *(const float2*)(add1 + i1);
                v0.x += a0.x; v0.y += a0.y; v1.x += a1.x; v1.y += a1.y;
            }
            if (add2) {
                float2 a0 = *(const float2*)(add2 + i0);
                float2 a1 = *(const float2*)(add2 + i1);
                v0.x += a0.x; v0.y += a0.y; v1.x += a1.x; v1.y += a1.y;
            }
            *(float2*)(D + i0) = v0;
            *(float2*)(D + i1) = v1;
        }
    }
}

// ------------------------- gist cross-attention (16 kv tokens) ---------------
__global__ void attn_kernel(const float* __restrict__ Q,
                            const float* __restrict__ Kh,
                            const float* __restrict__ V,
                            __nv_bfloat16* __restrict__ ch,
                            __nv_bfloat16* __restrict__ cl) {
    __shared__ float Ks[KGIST][HDIM];
    __shared__ float Vs[KGIST][HDIM];
    const int h = blockIdx.y, b = blockIdx.z;
    const int t0 = blockIdx.x * 32;
    for (int j = threadIdx.x; j < KGIST * HDIM; j += 256) {
        int k = j >> 7, c = j & 127;
        Ks[k][c] = Kh[(size_t)(b * KGIST + k) * DMODEL + h * HDIM + c];
        Vs[k][c] = V [(size_t)(b * KGIST + k) * DMODEL + h * HDIM + c];
    }
    __syncthreads();
    const int w = threadIdx.x >> 5, lane = threadIdx.x & 31;
    const float scale = 0.08838834764831845f;
    for (int it = 0; it < 4; it++) {
        int t = t0 + w * 4 + it;
        size_t base = ((size_t)(b * TLEN + t)) * DMODEL + h * HDIM + lane * 4;
        float q0 = Q[base], q1 = Q[base + 1], q2 = Q[base + 2], q3 = Q[base + 3];
        float sc[KGIST];
        #pragma unroll
        for (int k = 0; k < KGIST; k++) {
            float ps = q0 * Ks[k][lane * 4] + q1 * Ks[k][lane * 4 + 1]
                     + q2 * Ks[k][lane * 4 + 2] + q3 * Ks[k][lane * 4 + 3];
            #pragma unroll
            for (int o = 16; o > 0; o >>= 1) ps += __shfl_xor_sync(0xffffffffu, ps, o);
            sc[k] = ps * scale;
        }
        float mx = sc[0];
        #pragma unroll
        for (int k = 1; k < KGIST; k++) mx = fmaxf(mx, sc[k]);
        float ssum = 0.f;
        #pragma unroll
        for (int k = 0; k < KGIST; k++) { sc[k] = expf(sc[k] - mx); ssum += sc[k]; }
        float inv = 1.f / ssum;
        float c0 = 0.f, c1 = 0.f, c2 = 0.f, c3 = 0.f;
        #pragma unroll
        for (int k = 0; k < KGIST; k++) {
            float wk = sc[k] * inv;
            c0 += wk * Vs[k][lane * 4];
            c1 += wk * Vs[k][lane * 4 + 1];
            c2 += wk * Vs[k][lane * 4 + 2];
            c3 += wk * Vs[k][lane * 4 + 3];
        }
        __nv_bfloat16 hh, ll;
        split_hi_lo(c0, hh, ll); ch[base]     = hh; cl[base]     = ll;
        split_hi_lo(c1, hh, ll); ch[base + 1] = hh; cl[base + 1] = ll;
        split_hi_lo(c2, hh, ll); ch[base + 2] = hh; cl[base + 2] = ll;
        split_hi_lo(c3, hh, ll); ch[base + 3] = hh; cl[base + 3] = ll;
    }
}

// ------------------------- launcher -----------------------------------------
extern "C" void kernel_launch(void* const* d_in, const int* in_sizes, int n_in,
                              void* d_out, int out_size) {
    const float* x             = (const float*)d_in[0];
    const float* gist_theta    = (const float*)d_in[1];
    const float* gist_mag      = (const float*)d_in[2];
    const float* gist_weights  = (const float*)d_in[3];
    const float* ln_sheaf_w    = (const float*)d_in[4];
    const float* ln_sheaf_b    = (const float*)d_in[5];
    const float* sheaf_thetas  = (const float*)d_in[6];
    const float* alpha         = (const float*)d_in[7];
    const float* corr_W        = (const float*)d_in[8];
    const float* ln_gist_w     = (const float*)d_in[9];
    const float* ln_gist_b     = (const float*)d_in[10];
    const float* gist_strength = (const float*)d_in[11];
    const float* gr_ln_w       = (const float*)d_in[12];
    const float* gr_ln_b       = (const float*)d_in[13];
    const float* ln_gca_w      = (const float*)d_in[14];
    const float* ln_gca_b      = (const float*)d_in[15];
    const float* Wq            = (const float*)d_in[16];
    const float* Wk            = (const float*)d_in[17];
    const float* Wv            = (const float*)d_in[18];
    const float* Wo            = (const float*)d_in[19];
    const float* gist_up_W     = (const float*)d_in[20];
    const float* gist_up_b     = (const float*)d_in[21];
    float* out = (float*)d_out;

    float *y, *u, *x1, *x2, *q, *feat, *part, *repr, *kh, *v, *shc, *shs, *gc, *gs;
    __nv_bfloat16 *ahi, *alo, *whi, *wlo;
    cudaGetSymbolAddress((void**)&y,    g_y);
    cudaGetSymbolAddress((void**)&u,    g_u);
    cudaGetSymbolAddress((void**)&x1,   g_x1);
    cudaGetSymbolAddress((void**)&x2,   g_x2);
    cudaGetSymbolAddress((void**)&q,    g_q);
    cudaGetSymbolAddress((void**)&feat, g_feat);
    cudaGetSymbolAddress((void**)&part, g_part);
    cudaGetSymbolAddress((void**)&repr, g_repr);
    cudaGetSymbolAddress((void**)&kh,   g_kh);
    cudaGetSymbolAddress((void**)&v,    g_v);
    cudaGetSymbolAddress((void**)&shc,  g_shc);
    cudaGetSymbolAddress((void**)&shs,  g_shs);
    cudaGetSymbolAddress((void**)&gc,   g_gc);
    cudaGetSymbolAddress((void**)&gs,   g_gs);
    cudaGetSymbolAddress((void**)&ahi,  g_ahi);
    cudaGetSymbolAddress((void**)&alo,  g_alo);
    cudaGetSymbolAddress((void**)&whi,  g_whi);
    cudaGetSymbolAddress((void**)&wlo,  g_wlo);

    cudaFuncSetAttribute(gemm_bf16_kernel,
                         cudaFuncAttributeMaxDynamicSharedMemorySize, SMEM_GEMM);

    dim3 ggemm(DMODEL / 256, NROWS / 128);   // (8, 64)
    const int wsplit4 = DMODEL * DMODEL / 4;
    const int kp_up = (KUP + SKC - 1) / SKC;       // 17
    const int kp_d  = DMODEL / SKC;                // 32
    const int redgrid = (64 * DMODEL + 255) / 256; // 512

    // prep
    prep_sheaf_cs_kernel<<<16, 256>>>(sheaf_thetas, shc, shs);
    gist_theta_kernel<<<BATCH, 256>>>(gist_theta, gist_mag, gist_weights, gist_strength, gc, gs);
    feat_kernel<<<BATCH * KGIST, 256>>>(gist_theta, gist_mag, feat);

    // gist K/V path: split-K small GEMMs (deterministic two-phase)
    smallgemm_kernel<<<dim3(32, kp_up), 256>>>(feat, KUP, gist_up_W, KUP, part, KUP);
    skreduce_kernel<<<redgrid, 256>>>(part, kp_up, gist_up_b, repr);
    smallgemm_kernel<<<dim3(32, kp_d), 256>>>(repr, DMODEL, Wk, DMODEL, part, DMODEL);
    skreduce_kernel<<<redgrid, 256>>>(part, kp_d, nullptr, kh);
    smallgemm_kernel<<<dim3(32, kp_d), 256>>>(repr, DMODEL, Wv, DMODEL, part, DMODEL);
    skreduce_kernel<<<redgrid, 256>>>(part, kp_d, nullptr, v);

    // stage 1: sheaf residual
    ln_kernel<<<NROWS, 256>>>(x, ln_sheaf_w, ln_sheaf_b, y, nullptr, nullptr);
    sheaf_kernel<<<NROWS, 256>>>(y, shc, shs, alpha, u, ahi, alo);
    split_kernel<<<(wsplit4 + 255) / 256, 256>>>(corr_W, whi, wlo, wsplit4);
    gemm_bf16_kernel<<<ggemm, 256, SMEM_GEMM>>>(ahi, alo, whi, wlo, x1, x, u);

    // stage 2: gist rotation residual (fused)
    gist_rot_kernel<<<NROWS, 256>>>(x1, ln_gist_w, ln_gist_b, gr_ln_w, gr_ln_b, gc, gs, x2);

    // stage 3: gist cross-attention residual
    ln_kernel<<<NROWS, 256>>>(x2, ln_gca_w, ln_gca_b, nullptr, ahi, alo);
    split_kernel<<<(wsplit4 + 255) / 256, 256>>>(Wq, whi, wlo, wsplit4);
    gemm_bf16_kernel<<<ggemm, 256, SMEM_GEMM>>>(ahi, alo, whi, wlo, q, nullptr, nullptr);
    attn_kernel<<<dim3(TLEN / 32, NHEADS, BATCH), 256>>>(q, kh, v, ahi, alo);
    split_kernel<<<(wsplit4 + 255) / 256, 256>>>(Wo, whi, wlo, wsplit4);
    gemm_bf16_kernel<<<ggemm, 256, SMEM_GEMM>>>(ahi, alo, whi, wlo, out, x2, nullptr);

    (void)in_sizes; (void)n_in; (void)out_size;
}

// round 10
// speedup vs baseline: 1.3573x; 1.3573x over previous
#include <cuda_runtime.h>
#include <cuda_fp16.h>
#include <cuda_bf16.h>
#include <cuda.h>
#include <math.h>
#include <cstdint>

// Problem constants
#define BATCH 4
#define TLEN 2048
#define DMODEL 2048
#define DHALF 1024
#define NROWS (BATCH * TLEN)          // 8192
#define KGIST 16
#define NHEADS 16
#define HDIM 128
#define KUP 1025                       // gist_up feature dim (dh + 1)
#define MAXPART 32

// ------------------------- scratch (device globals; no allocation) ---------
__device__ float g_y [NROWS * DMODEL];
__device__ float g_u [NROWS * DMODEL];
__device__ float g_x1[NROWS * DMODEL];
__device__ float g_x2[NROWS * DMODEL];
__device__ float g_q [NROWS * DMODEL];
__device__ __half g_ahi[NROWS * DMODEL];
__device__ __half g_alo[NROWS * DMODEL];
__device__ __half g_w16[DMODEL * DMODEL];
__device__ float g_feat[BATCH * KGIST * KUP];
__device__ float g_part[MAXPART * BATCH * KGIST * DMODEL];   // split-K partials
__device__ float g_repr[BATCH * KGIST * DMODEL];
__device__ float g_kh  [BATCH * KGIST * DMODEL];
__device__ float g_v   [BATCH * KGIST * DMODEL];
__device__ float g_shc[4 * DHALF];
__device__ float g_shs[4 * DHALF];
__device__ float g_gc [BATCH * DHALF];
__device__ float g_gs [BATCH * DHALF];

// ------------------------- helpers -----------------------------------------
__device__ __forceinline__ uint32_t smem_u32(const void* p) {
    uint32_t a;
    asm("{ .reg .u64 t; cvta.to.shared.u64 t, %1; cvt.u32.u64 %0, t; }" : "=r"(a) : "l"(p));
    return a;
}

__device__ __forceinline__ void cpasync16(uint32_t dst, const void* src) {
    asm volatile("cp.async.cg.shared.global [%0], [%1], 16;" :: "r"(dst), "l"(src));
}
#define CP_COMMIT() asm volatile("cp.async.commit_group;" ::: "memory")
#define CP_WAIT(n)  asm volatile("cp.async.wait_group %0;" :: "n"(n) : "memory")

__device__ __forceinline__ float block_reduce_sum256(float v) {
    __shared__ float sb[8];
    int lane = threadIdx.x & 31, wid = threadIdx.x >> 5;
    #pragma unroll
    for (int o = 16; o > 0; o >>= 1) v += __shfl_xor_sync(0xffffffffu, v, o);
    if (lane == 0) sb[wid] = v;
    __syncthreads();
    float r = 0.f;
    #pragma unroll
    for (int i = 0; i < 8; i++) r += sb[i];
    __syncthreads();
    return r;
}

__device__ __forceinline__ void split_hi_lo_h(float v, __half& h, __half& l) {
    h = __float2half(v);
    l = __float2half(v - __half2float(h));
}

__device__ __forceinline__ void mma16816h(float* d, const uint32_t* a, uint32_t b0, uint32_t b1) {
    asm volatile(
        "mma.sync.aligned.m16n8k16.row.col.f32.f16.f16.f32 "
        "{%0,%1,%2,%3}, {%4,%5,%6,%7}, {%8,%9}, {%0,%1,%2,%3};"
        : "+f"(d[0]), "+f"(d[1]), "+f"(d[2]), "+f"(d[3])
        : "r"(a[0]), "r"(a[1]), "r"(a[2]), "r"(a[3]), "r"(b0), "r"(b1));
}

__device__ __forceinline__ void ldsm_x4(uint32_t* r, uint32_t addr) {
    asm volatile("ldmatrix.sync.aligned.m8n8.x4.shared.b16 {%0,%1,%2,%3}, [%4];"
                 : "=r"(r[0]), "=r"(r[1]), "=r"(r[2]), "=r"(r[3]) : "r"(addr));
}

// ------------------------- small prep kernels -------------------------------
__global__ void prep_sheaf_cs_kernel(const float* __restrict__ thetas,
                                     float* __restrict__ c, float* __restrict__ s) {
    int i = blockIdx.x * 256 + threadIdx.x;
    if (i < 4 * DHALF) { float th = thetas[i]; c[i] = cosf(th); s[i] = sinf(th); }
}

__global__ void gist_theta_kernel(const float* __restrict__ gtheta,
                                  const float* __restrict__ gmag,
                                  const float* __restrict__ gw,
                                  const float* __restrict__ gstrength,
                                  float* __restrict__ gc, float* __restrict__ gs) {
    int b = blockIdx.x;
    float wk[KGIST]; float wsum = 0.f;
    #pragma unroll
    for (int k = 0; k < KGIST; k++) { wk[k] = gw[b * KGIST + k] * gmag[b * KGIST + k]; wsum += wk[k]; }
    float inv = 1.f / (wsum + 1e-8f);
    float sig = 1.f / (1.f + expf(-gstrength[0]));
    for (int p = threadIdx.x; p < DHALF; p += 256) {
        float th = 0.f;
        #pragma unroll
        for (int k = 0; k < KGIST; k++) th += (wk[k] * inv) * gtheta[(size_t)(b * KGIST + k) * DHALF + p];
        th *= sig;
        gc[b * DHALF + p] = cosf(th);
        gs[b * DHALF + p] = sinf(th);
    }
}

__global__ void feat_kernel(const float* __restrict__ gtheta,
                            const float* __restrict__ gmag,
                            float* __restrict__ feat) {
    int r = blockIdx.x;           // 0..63
    for (int f = threadIdx.x; f < KUP; f += 256) {
        float v = (f < DHALF) ? gtheta[(size_t)r * DHALF + f] : gmag[r];
        feat[(size_t)r * KUP + f] = v;
    }
}

// fp32 -> fp16 weight conversion
__global__ void w16_kernel(const float* __restrict__ in,
                           __half* __restrict__ out, int n4) {
    int i = blockIdx.x * 256 + threadIdx.x;
    if (i >= n4) return;
    float4 v = ((const float4*)in)[i];
    __half2 a = __floats2half2_rn(v.x, v.y);
    __half2 b = __floats2half2_rn(v.z, v.w);
    ((__half2*)out)[2 * i]     = a;
    ((__half2*)out)[2 * i + 1] = b;
}

// ------------------------- LayerNorm (optionally emits fp16 hi/lo) ---------
__global__ void ln_kernel(const float* __restrict__ in,
                          const float* __restrict__ w,
                          const float* __restrict__ b,
                          float* __restrict__ outf,
                          __half* __restrict__ outh,
                          __half* __restrict__ outl) {
    int row = blockIdx.x;
    const float* p = in + (size_t)row * DMODEL;
    float v[8];
    #pragma unroll
    for (int j = 0; j < 8; j++) v[j] = p[threadIdx.x + 256 * j];
    float s = 0.f;
    #pragma unroll
    for (int j = 0; j < 8; j++) s += v[j];
    float mean = block_reduce_sum256(s) * (1.f / DMODEL);
    float q = 0.f;
    #pragma unroll
    for (int j = 0; j < 8; j++) { float d = v[j] - mean; q += d * d; }
    float var = block_reduce_sum256(q) * (1.f / DMODEL);
    float rstd = rsqrtf(var + 1e-5f);
    #pragma unroll
    for (int j = 0; j < 8; j++) {
        int i = threadIdx.x + 256 * j;
        float val = (v[j] - mean) * rstd * w[i] + b[i];
        size_t idx = (size_t)row * DMODEL + i;
        if (outf) outf[idx] = val;
        if (outh) {
            __half h, l; split_hi_lo_h(val, h, l);
            outh[idx] = h; outl[idx] = l;
        }
    }
}

// ------------------------- sheaf (writes fp32 u + fp16 hi/lo) --------------
__global__ void sheaf_kernel(const float* __restrict__ y,
                             const float* __restrict__ ctab,
                             const float* __restrict__ stab,
                             const float* __restrict__ alpha_p,
                             float* __restrict__ u,
                             __half* __restrict__ uh,
                             __half* __restrict__ ul) {
    int row = blockIdx.x;
    int t = row & (TLEN - 1);
    float a = fabsf(alpha_p[0]);
    const float* yr = y + (size_t)row * DMODEL;
    #pragma unroll
    for (int jj = 0; jj < 4; jj++) {
        int p = threadIdx.x + 256 * jj;
        float r0 = yr[p], i0 = yr[p + DHALF];
        float lr = 4.f * r0, li = 4.f * i0;
        #pragma unroll
        for (int idx = 0; idx < 4; idx++) {
            int delta = idx - 3;
            float rs, is;
            if (delta == 0) { rs = r0; is = i0; }
            else if (t + delta >= 0) {
                const float* ys = y + (size_t)(row + delta) * DMODEL;
                rs = ys[p]; is = ys[p + DHALF];
            } else { rs = 0.f; is = 0.f; }
            float c = ctab[idx * DHALF + p], s = stab[idx * DHALF + p];
            lr -= c * rs + s * is;
            li -= c * is - s * rs;
        }
        float outr = r0 - a * lr, outi = i0 - a * li;
        size_t br = (size_t)row * DMODEL + p, bi = br + DHALF;
        u[br] = outr; u[bi] = outi;
        __half h, l;
        split_hi_lo_h(outr, h, l); uh[br] = h; ul[br] = l;
        split_hi_lo_h(outi, h, l); uh[bi] = h; ul[bi] = l;
    }
}

// ------------------------- fused gist rotation block ------------------------
__global__ void gist_rot_kernel(const float* __restrict__ x1,
                                const float* __restrict__ lw, const float* __restrict__ lb,
                                const float* __restrict__ grw, const float* __restrict__ grb,
                                const float* __restrict__ gc, const float* __restrict__ gs,
                                float* __restrict__ x2) {
    int row = blockIdx.x;
    int b = row >> 11;
    const float* p = x1 + (size_t)row * DMODEL;
    float xr[4], xi[4];
    #pragma unroll
    for (int jj = 0; jj < 4; jj++) {
        int q = threadIdx.x + 256 * jj;
        xr[jj] = p[q]; xi[jj] = p[q + DHALF];
    }
    float s1 = 0.f;
    #pragma unroll
    for (int jj = 0; jj < 4; jj++) s1 += xr[jj] + xi[jj];
    float m1 = block_reduce_sum256(s1) * (1.f / DMODEL);
    float q1 = 0.f;
    #pragma unroll
    for (int jj = 0; jj < 4; jj++) {
        float dr = xr[jj] - m1, di = xi[jj] - m1;
        q1 += dr * dr + di * di;
    }
    float rstd1 = rsqrtf(block_reduce_sum256(q1) * (1.f / DMODEL) + 1e-5f);

    float xnr[4], xni[4], rr[4], ri[4];
    #pragma unroll
    for (int jj = 0; jj < 4; jj++) {
        int q = threadIdx.x + 256 * jj;
        xnr[jj] = (xr[jj] - m1) * rstd1 * lw[q] + lb[q];
        xni[jj] = (xi[jj] - m1) * rstd1 * lw[q + DHALF] + lb[q + DHALF];
        float c = gc[b * DHALF + q], sn = gs[b * DHALF + q];
        rr[jj] = xnr[jj] * c - xni[jj] * sn;
        ri[jj] = xnr[jj] * sn + xni[jj] * c;
    }
    float s2 = 0.f;
    #pragma unroll
    for (int jj = 0; jj < 4; jj++) s2 += rr[jj] + ri[jj];
    float m2 = block_reduce_sum256(s2) * (1.f / DMODEL);
    float q2 = 0.f;
    #pragma unroll
    for (int jj = 0; jj < 4; jj++) {
        float dr = rr[jj] - m2, di = ri[jj] - m2;
        q2 += dr * dr + di * di;
    }
    float rstd2 = rsqrtf(block_reduce_sum256(q2) * (1.f / DMODEL) + 1e-5f);

    #pragma unroll
    for (int jj = 0; jj < 4; jj++) {
        int q = threadIdx.x + 256 * jj;
        float outr = xr[jj] + (rr[jj] - m2) * rstd2 * grw[q] + grb[q] - xnr[jj];
        float outi = xi[jj] + (ri[jj] - m2) * rstd2 * grw[q + DHALF] + grb[q + DHALF] - xni[jj];
        x2[(size_t)row * DMODEL + q]         = outr;
        x2[(size_t)row * DMODEL + q + DHALF] = outi;
    }
}

// ------------------- split-K small GEMM (M=64, N=2048) ----------------------
#define SKC 64
__global__ __launch_bounds__(256, 4)
void smallgemm_kernel(const float* __restrict__ A, int lda,
                      const float* __restrict__ W, int ldw,
                      float* __restrict__ part, int Kdim) {
    __shared__ float Fs[64][SKC + 1];
    __shared__ float Ws[64][SKC + 1];
    const int n0 = blockIdx.x * 64;
    const int k0 = blockIdx.y * SKC;
    const int tid = threadIdx.x;

    for (int idx = tid; idx < 64 * SKC; idx += 256) {
        int r = idx >> 6, c = idx & 63;
        int k = k0 + c;
        Fs[r][c] = (k < Kdim) ? A[(size_t)r * lda + k] : 0.f;
        Ws[r][c] = (k < Kdim) ? W[(size_t)(n0 + r) * ldw + k] : 0.f;
    }
    __syncthreads();

    const int tx = tid & 15, ty = tid >> 4;
    float acc[4][4];
    #pragma unroll
    for (int i = 0; i < 4; i++)
        #pragma unroll
        for (int j = 0; j < 4; j++) acc[i][j] = 0.f;

    for (int k = 0; k < SKC; k++) {
        float ra[4], rb[4];
        #pragma unroll
        for (int i = 0; i < 4; i++) ra[i] = Fs[ty * 4 + i][k];
        #pragma unroll
        for (int j = 0; j < 4; j++) rb[j] = Ws[tx * 4 + j][k];
        #pragma unroll
        for (int i = 0; i < 4; i++)
            #pragma unroll
            for (int j = 0; j < 4; j++) acc[i][j] += ra[i] * rb[j];
    }

    float* pz = part + (size_t)blockIdx.y * (64 * DMODEL);
    #pragma unroll
    for (int i = 0; i < 4; i++)
        #pragma unroll
        for (int j = 0; j < 4; j++)
            pz[(size_t)(ty * 4 + i) * DMODEL + n0 + tx * 4 + j] = acc[i][j];
}

__global__ void skreduce_kernel(const float* __restrict__ part, int nparts,
                                const float* __restrict__ bias,
                                float* __restrict__ out) {
    int idx = blockIdx.x * 256 + threadIdx.x;
    if (idx >= 64 * DMODEL) return;
    float s = bias ? bias[idx & (DMODEL - 1)] : 0.f;
    for (int z = 0; z < nparts; z++) s += part[(size_t)z * (64 * DMODEL) + idx];
    out[idx] = s;
}

// ------------------------- fp16 HMMA 2-term GEMM ----------------------------
// D[m,n] = sum_k (Ahi+Alo)[m,k] * W16[n,k]   (A exact to ~22 bits; W fp16)
// CTA tile 128x256, BK=64, 8 warps as 2m x 4n, warp tile 64x64, ldmatrix.
#define GBK 64
#define ROWP 72
#define OFF_ALO   (128 * ROWP)                 // 9216 elements
#define OFF_W     (256 * ROWP)                 // 18432 elements
#define STAGE_EL  (512 * ROWP)                 // 36864 elements
#define STAGE_B   (STAGE_EL * 2)               // 73728 bytes
#define SMEM_GEMM (2 * STAGE_B)                // 147456 bytes

__global__ __launch_bounds__(256, 1)
void gemm_f16_kernel(const __half* __restrict__ Ahi,
                     const __half* __restrict__ Alo,
                     const __half* __restrict__ W16,
                     float* __restrict__ D,
                     const float* __restrict__ add1,
                     const float* __restrict__ add2) {
    extern __shared__ __half sm[];
    const int tid  = threadIdx.x;
    const int lane = tid & 31;
    const int warp = tid >> 5;
    const int wm = warp & 1;            // 2 m-tiles of 64
    const int wn = warp >> 1;           // 4 n-tiles of 64
    const int m0 = blockIdx.y * 128, n0 = blockIdx.x * 256;
    const uint32_t smb = smem_u32(sm);

    float acc[4][8][4];
    #pragma unroll
    for (int mt = 0; mt < 4; mt++)
        #pragma unroll
        for (int nt = 0; nt < 8; nt++)
            #pragma unroll
            for (int j = 0; j < 4; j++) acc[mt][nt][j] = 0.f;

    const int NCHUNK = DMODEL / GBK;    // 32

    const int a_row = lane & 15;
    const int a_k8  = (lane >= 16) ? 8 : 0;
    const int b_row = (lane & 7) + ((lane >= 16) ? 8 : 0);
    const int b_k8  = ((lane >> 3) & 1) ? 8 : 0;

    auto issue_stage = [&](int kc, uint32_t sbase) {
        const int k0 = kc * GBK;
        #pragma unroll
        for (int i = 0; i < 8; i++) {                  // A hi+lo: 2048 cp16
            int idx = tid + i * 256;
            int row = idx >> 3, ch = idx & 7;          // row 0..255
            const __half* src = (row < 128)
                ? Ahi + (size_t)(m0 + row) * DMODEL + k0 + ch * 8
                : Alo + (size_t)(m0 + row - 128) * DMODEL + k0 + ch * 8;
            cpasync16(sbase + (uint32_t)(row * ROWP + ch * 8) * 2, src);
        }
        #pragma unroll
        for (int i = 0; i < 8; i++) {                  // W: 2048 cp16
            int idx = tid + i * 256;
            int row = idx >> 3, ch = idx & 7;          // row 0..255
            cpasync16(sbase + (uint32_t)(OFF_W + row * ROWP + ch * 8) * 2,
                      W16 + (size_t)(n0 + row) * DMODEL + k0 + ch * 8);
        }
    };

    issue_stage(0, smb);
    CP_COMMIT();

    for (int kc = 0; kc < NCHUNK; kc++) {
        if (kc + 1 < NCHUNK) {
            issue_stage(kc + 1, smb + ((kc + 1) & 1) * STAGE_B);
            CP_COMMIT();
            CP_WAIT(1);
        } else {
            CP_WAIT(0);
        }
        __syncthreads();

        const uint32_t sbase = smb + (kc & 1) * STAGE_B;

        #pragma unroll
        for (int ks = 0; ks < 4; ks++) {
            const int kb = ks * 16;
            uint32_t ah[4][4], al[4][4];
            #pragma unroll
            for (int mt = 0; mt < 4; mt++) {
                int rowe = (wm * 64 + mt * 16 + a_row) * ROWP + kb + a_k8;
                ldsm_x4(ah[mt], sbase + (uint32_t)rowe * 2);
                ldsm_x4(al[mt], sbase + (uint32_t)(rowe + OFF_ALO) * 2);
            }
            #pragma unroll
            for (int ntp = 0; ntp < 4; ntp++) {
                uint32_t bh[4];
                int rowe = OFF_W + (wn * 64 + ntp * 16 + b_row) * ROWP + kb + b_k8;
                ldsm_x4(bh, sbase + (uint32_t)rowe * 2);
                #pragma unroll
                for (int mt = 0; mt < 4; mt++) {
                    mma16816h(acc[mt][2 * ntp],     ah[mt], bh[0], bh[1]);
                    mma16816h(acc[mt][2 * ntp],     al[mt], bh[0], bh[1]);
                    mma16816h(acc[mt][2 * ntp + 1], ah[mt], bh[2], bh[3]);
                    mma16816h(acc[mt][2 * ntp + 1], al[mt], bh[2], bh[3]);
                }
            }
        }
        __syncthreads();
    }

    const int r  = lane >> 2;
    const int c2 = lane & 3;
    #pragma unroll
    for (int mt = 0; mt < 4; mt++) {
        #pragma unroll
        for (int nt = 0; nt < 8; nt++) {
            int row0 = m0 + wm * 64 + mt * 16 + r;
            int col  = n0 + wn * 64 + nt * 8 + c2 * 2;
            size_t i0 = (size_t)row0 * DMODEL + col;
            size_t i1 = i0 + (size_t)8 * DMODEL;
            float2 v0 = make_float2(acc[mt][nt][0], acc[mt][nt][1]);
            float2 v1 = make_float2(acc[mt][nt][2], acc[mt][nt][3]);
            if (add1) {
                float2 a0 = *(const float2*)(add1 + i0);
                float2 a1 = *(const float2*)(add1 + i1);
                v0.x += a0.x; v0.y += a0.y; v1.x += a1.x; v1.y += a1.y;
            }
            if (add2) {
                float2 a0 = *(const float2*)(add2 + i0);
                float2 a1 = *(const float2*)(add2 + i1);
                v0.x += a0.x; v0.y += a0.y; v1.x += a1.x; v1.y += a1.y;
            }
            *(float2*)(D + i0) = v0;
            *(float2*)(D + i1) = v1;
        }
    }
}

// ------------------------- gist cross-attention (16 kv tokens) ---------------
__global__ void attn_kernel(const float* __restrict__ Q,
                            const float* __restrict__ Kh,
                            const float* __restrict__ V,
                            __half* __restrict__ ch,
                            __half* __restrict__ cl) {
    __shared__ float Ks[KGIST][HDIM];
    __shared__ float Vs[KGIST][HDIM];
    const int h = blockIdx.y, b = blockIdx.z;
    const int t0 = blockIdx.x * 32;
    for (int j = threadIdx.x; j < KGIST * HDIM; j += 256) {
        int k = j >> 7, c = j & 127;
        Ks[k][c] = Kh[(size_t)(b * KGIST + k) * DMODEL + h * HDIM + c];
        Vs[k][c] = V [(size_t)(b * KGIST + k) * DMODEL + h * HDIM + c];
    }
    __syncthreads();
    const int w = threadIdx.x >> 5, lane = threadIdx.x & 31;
    const float scale = 0.08838834764831845f;
    for (int it = 0; it < 4; it++) {
        int t = t0 + w * 4 + it;
        size_t base = ((size_t)(b * TLEN + t)) * DMODEL + h * HDIM + lane * 4;
        float q0 = Q[base], q1 = Q[base + 1], q2 = Q[base + 2], q3 = Q[base + 3];
        float sc[KGIST];
        #pragma unroll
        for (int k = 0; k < KGIST; k++) {
            float ps = q0 * Ks[k][lane * 4] + q1 * Ks[k][lane * 4 + 1]
                     + q2 * Ks[k][lane * 4 + 2] + q3 * Ks[k][lane * 4 + 3];
            #pragma unroll
            for (int o = 16; o > 0; o >>= 1) ps += __shfl_xor_sync(0xffffffffu, ps, o);
            sc[k] = ps * scale;
        }
        float mx = sc[0];
        #pragma unroll
        for (int k = 1; k < KGIST; k++) mx = fmaxf(mx, sc[k]);
        float ssum = 0.f;
        #pragma unroll
        for (int k = 0; k < KGIST; k++) { sc[k] = expf(sc[k] - mx); ssum += sc[k]; }
        float inv = 1.f / ssum;
        float c0 = 0.f, c1 = 0.f, c2 = 0.f, c3 = 0.f;
        #pragma unroll
        for (int k = 0; k < KGIST; k++) {
            float wk = sc[k] * inv;
            c0 += wk * Vs[k][lane * 4];
            c1 += wk * Vs[k][lane * 4 + 1];
            c2 += wk * Vs[k][lane * 4 + 2];
            c3 += wk * Vs[k][lane * 4 + 3];
        }
        __half hh, ll;
        split_hi_lo_h(c0, hh, ll); ch[base]     = hh; cl[base]     = ll;
        split_hi_lo_h(c1, hh, ll); ch[base + 1] = hh; cl[base + 1] = ll;
        split_hi_lo_h(c2, hh, ll); ch[base + 2] = hh; cl[base + 2] = ll;
        split_hi_lo_h(c3, hh, ll); ch[base + 3] = hh; cl[base + 3] = ll;
    }
}

// ------------------------- launcher -----------------------------------------
extern "C" void kernel_launch(void* const* d_in, const int* in_sizes, int n_in,
                              void* d_out, int out_size) {
    const float* x             = (const float*)d_in[0];
    const float* gist_theta    = (const float*)d_in[1];
    const float* gist_mag      = (const float*)d_in[2];
    const float* gist_weights  = (const float*)d_in[3];
    const float* ln_sheaf_w    = (const float*)d_in[4];
    const float* ln_sheaf_b    = (const float*)d_in[5];
    const float* sheaf_thetas  = (const float*)d_in[6];
    const float* alpha         = (const float*)d_in[7];
    const float* corr_W        = (const float*)d_in[8];
    const float* ln_gist_w     = (const float*)d_in[9];
    const float* ln_gist_b     = (const float*)d_in[10];
    const float* gist_strength = (const float*)d_in[11];
    const float* gr_ln_w       = (const float*)d_in[12];
    const float* gr_ln_b       = (const float*)d_in[13];
    const float* ln_gca_w      = (const float*)d_in[14];
    const float* ln_gca_b      = (const float*)d_in[15];
    const float* Wq            = (const float*)d_in[16];
    const float* Wk            = (const float*)d_in[17];
    const float* Wv            = (const float*)d_in[18];
    const float* Wo            = (const float*)d_in[19];
    const float* gist_up_W     = (const float*)d_in[20];
    const float* gist_up_b     = (const float*)d_in[21];
    float* out = (float*)d_out;

    float *y, *u, *x1, *x2, *q, *feat, *part, *repr, *kh, *v, *shc, *shs, *gc, *gs;
    __half *ahi, *alo, *w16;
    cudaGetSymbolAddress((void**)&y,    g_y);
    cudaGetSymbolAddress((void**)&u,    g_u);
    cudaGetSymbolAddress((void**)&x1,   g_x1);
    cudaGetSymbolAddress((void**)&x2,   g_x2);
    cudaGetSymbolAddress((void**)&q,    g_q);
    cudaGetSymbolAddress((void**)&feat, g_feat);
    cudaGetSymbolAddress((void**)&part, g_part);
    cudaGetSymbolAddress((void**)&repr, g_repr);
    cudaGetSymbolAddress((void**)&kh,   g_kh);
    cudaGetSymbolAddress((void**)&v,    g_v);
    cudaGetSymbolAddress((void**)&shc,  g_shc);
    cudaGetSymbolAddress((void**)&shs,  g_shs);
    cudaGetSymbolAddress((void**)&gc,   g_gc);
    cudaGetSymbolAddress((void**)&gs,   g_gs);
    cudaGetSymbolAddress((void**)&ahi,  g_ahi);
    cudaGetSymbolAddress((void**)&alo,  g_alo);
    cudaGetSymbolAddress((void**)&w16,  g_w16);

    cudaFuncSetAttribute(gemm_f16_kernel,
                         cudaFuncAttributeMaxDynamicSharedMemorySize, SMEM_GEMM);

    dim3 ggemm(DMODEL / 256, NROWS / 128);   // (8, 64)
    const int wsplit4 = DMODEL * DMODEL / 4;
    const int kp_up = (KUP + SKC - 1) / SKC;       // 17
    const int kp_d  = DMODEL / SKC;                // 32
    const int redgrid = (64 * DMODEL + 255) / 256; // 512

    // prep
    prep_sheaf_cs_kernel<<<16, 256>>>(sheaf_thetas, shc, shs);
    gist_theta_kernel<<<BATCH, 256>>>(gist_theta, gist_mag, gist_weights, gist_strength, gc, gs);
    feat_kernel<<<BATCH * KGIST, 256>>>(gist_theta, gist_mag, feat);

    // gist K/V path: split-K small GEMMs (deterministic two-phase)
    smallgemm_kernel<<<dim3(32, kp_up), 256>>>(feat, KUP, gist_up_W, KUP, part, KUP);
    skreduce_kernel<<<redgrid, 256>>>(part, kp_up, gist_up_b, repr);
    smallgemm_kernel<<<dim3(32, kp_d), 256>>>(repr, DMODEL, Wk, DMODEL, part, DMODEL);
    skreduce_kernel<<<redgrid, 256>>>(part, kp_d, nullptr, kh);
    smallgemm_kernel<<<dim3(32, kp_d), 256>>>(repr, DMODEL, Wv, DMODEL, part, DMODEL);
    skreduce_kernel<<<redgrid, 256>>>(part, kp_d, nullptr, v);

    // stage 1: sheaf residual
    ln_kernel<<<NROWS, 256>>>(x, ln_sheaf_w, ln_sheaf_b, y, nullptr, nullptr);
    sheaf_kernel<<<NROWS, 256>>>(y, shc, shs, alpha, u, ahi, alo);
    w16_kernel<<<(wsplit4 + 255) / 256, 256>>>(corr_W, w16, wsplit4);
    gemm_f16_kernel<<<ggemm, 256, SMEM_GEMM>>>(ahi, alo, w16, x1, x, u);

    // stage 2: gist rotation residual (fused)
    gist_rot_kernel<<<NROWS, 256>>>(x1, ln_gist_w, ln_gist_b, gr_ln_w, gr_ln_b, gc, gs, x2);

    // stage 3: gist cross-attention residual
    ln_kernel<<<NROWS, 256>>>(x2, ln_gca_w, ln_gca_b, nullptr, ahi, alo);
    w16_kernel<<<(wsplit4 + 255) / 256, 256>>>(Wq, w16, wsplit4);
    gemm_f16_kernel<<<ggemm, 256, SMEM_GEMM>>>(ahi, alo, w16, q, nullptr, nullptr);
    attn_kernel<<<dim3(TLEN / 32, NHEADS, BATCH), 256>>>(q, kh, v, ahi, alo);
    w16_kernel<<<(wsplit4 + 255) / 256, 256>>>(Wo, w16, wsplit4);
    gemm_f16_kernel<<<ggemm, 256, SMEM_GEMM>>>(ahi, alo, w16, out, x2, nullptr);

    (void)in_sizes; (void)n_in; (void)out_size;
}

// round 12
// speedup vs baseline: 1.9434x; 1.4318x over previous
#include <cuda_runtime.h>
#include <cuda_fp16.h>
#include <cuda.h>
#include <math.h>
#include <cstdint>

// Problem constants
#define BATCH 4
#define TLEN 2048
#define DMODEL 2048
#define DHALF 1024
#define NROWS (BATCH * TLEN)          // 8192
#define KGIST 16
#define NHEADS 16
#define HDIM 128
#define KUP 1025                       // gist_up feature dim (dh + 1)
#define MAXPART 32

// ------------------------- scratch (device globals; no allocation) ---------
__device__ float g_y [NROWS * DMODEL];
__device__ float g_u [NROWS * DMODEL];
__device__ float g_x1[NROWS * DMODEL];
__device__ float g_x2[NROWS * DMODEL];
__device__ float g_q [NROWS * DMODEL];
__device__ __half g_a16[NROWS * DMODEL];
__device__ __half g_w16[DMODEL * DMODEL];
__device__ float g_feat[BATCH * KGIST * KUP];
__device__ float g_part[MAXPART * BATCH * KGIST * DMODEL];   // split-K partials
__device__ float g_repr[BATCH * KGIST * DMODEL];
__device__ float g_kh  [BATCH * KGIST * DMODEL];
__device__ float g_v   [BATCH * KGIST * DMODEL];
__device__ float g_shc[4 * DHALF];
__device__ float g_shs[4 * DHALF];
__device__ float g_gc [BATCH * DHALF];
__device__ float g_gs [BATCH * DHALF];

// ------------------------- helpers -----------------------------------------
__device__ __forceinline__ uint32_t smem_u32(const void* p) {
    uint32_t a;
    asm("{ .reg .u64 t; cvta.to.shared.u64 t, %1; cvt.u32.u64 %0, t; }" : "=r"(a) : "l"(p));
    return a;
}

__device__ __forceinline__ void cpasync16(uint32_t dst, const void* src) {
    asm volatile("cp.async.cg.shared.global [%0], [%1], 16;" :: "r"(dst), "l"(src));
}
#define CP_COMMIT() asm volatile("cp.async.commit_group;" ::: "memory")
#define CP_WAIT(n)  asm volatile("cp.async.wait_group %0;" :: "n"(n) : "memory")

__device__ __forceinline__ float block_reduce_sum256(float v) {
    __shared__ float sb[8];
    int lane = threadIdx.x & 31, wid = threadIdx.x >> 5;
    #pragma unroll
    for (int o = 16; o > 0; o >>= 1) v += __shfl_xor_sync(0xffffffffu, v, o);
    if (lane == 0) sb[wid] = v;
    __syncthreads();
    float r = 0.f;
    #pragma unroll
    for (int i = 0; i < 8; i++) r += sb[i];
    __syncthreads();
    return r;
}

__device__ __forceinline__ void mma16816h(float* d, const uint32_t* a, uint32_t b0, uint32_t b1) {
    asm volatile(
        "mma.sync.aligned.m16n8k16.row.col.f32.f16.f16.f32 "
        "{%0,%1,%2,%3}, {%4,%5,%6,%7}, {%8,%9}, {%0,%1,%2,%3};"
        : "+f"(d[0]), "+f"(d[1]), "+f"(d[2]), "+f"(d[3])
        : "r"(a[0]), "r"(a[1]), "r"(a[2]), "r"(a[3]), "r"(b0), "r"(b1));
}

__device__ __forceinline__ void ldsm_x4(uint32_t* r, uint32_t addr) {
    asm volatile("ldmatrix.sync.aligned.m8n8.x4.shared.b16 {%0,%1,%2,%3}, [%4];"
                 : "=r"(r[0]), "=r"(r[1]), "=r"(r[2]), "=r"(r[3]) : "r"(addr));
}

// ------------------------- small prep kernels -------------------------------
__global__ void prep_sheaf_cs_kernel(const float* __restrict__ thetas,
                                     float* __restrict__ c, float* __restrict__ s) {
    int i = blockIdx.x * 256 + threadIdx.x;
    if (i < 4 * DHALF) { float th = thetas[i]; c[i] = cosf(th); s[i] = sinf(th); }
}

__global__ void gist_theta_kernel(const float* __restrict__ gtheta,
                                  const float* __restrict__ gmag,
                                  const float* __restrict__ gw,
                                  const float* __restrict__ gstrength,
                                  float* __restrict__ gc, float* __restrict__ gs) {
    int b = blockIdx.x;
    float wk[KGIST]; float wsum = 0.f;
    #pragma unroll
    for (int k = 0; k < KGIST; k++) { wk[k] = gw[b * KGIST + k] * gmag[b * KGIST + k]; wsum += wk[k]; }
    float inv = 1.f / (wsum + 1e-8f);
    float sig = 1.f / (1.f + expf(-gstrength[0]));
    for (int p = threadIdx.x; p < DHALF; p += 256) {
        float th = 0.f;
        #pragma unroll
        for (int k = 0; k < KGIST; k++) th += (wk[k] * inv) * gtheta[(size_t)(b * KGIST + k) * DHALF + p];
        th *= sig;
        gc[b * DHALF + p] = cosf(th);
        gs[b * DHALF + p] = sinf(th);
    }
}

__global__ void feat_kernel(const float* __restrict__ gtheta,
                            const float* __restrict__ gmag,
                            float* __restrict__ feat) {
    int r = blockIdx.x;           // 0..63
    for (int f = threadIdx.x; f < KUP; f += 256) {
        float v = (f < DHALF) ? gtheta[(size_t)r * DHALF + f] : gmag[r];
        feat[(size_t)r * KUP + f] = v;
    }
}

// fp32 -> fp16 weight conversion
__global__ void w16_kernel(const float* __restrict__ in,
                           __half* __restrict__ out, int n4) {
    int i = blockIdx.x * 256 + threadIdx.x;
    if (i >= n4) return;
    float4 v = ((const float4*)in)[i];
    ((__half2*)out)[2 * i]     = __floats2half2_rn(v.x, v.y);
    ((__half2*)out)[2 * i + 1] = __floats2half2_rn(v.z, v.w);
}

// ------------------------- LayerNorm (optionally emits fp16) ---------------
__global__ void ln_kernel(const float* __restrict__ in,
                          const float* __restrict__ w,
                          const float* __restrict__ b,
                          float* __restrict__ outf,
                          __half* __restrict__ outh) {
    int row = blockIdx.x;
    const float* p = in + (size_t)row * DMODEL;
    float v[8];
    #pragma unroll
    for (int j = 0; j < 8; j++) v[j] = p[threadIdx.x + 256 * j];
    float s = 0.f;
    #pragma unroll
    for (int j = 0; j < 8; j++) s += v[j];
    float mean = block_reduce_sum256(s) * (1.f / DMODEL);
    float q = 0.f;
    #pragma unroll
    for (int j = 0; j < 8; j++) { float d = v[j] - mean; q += d * d; }
    float var = block_reduce_sum256(q) * (1.f / DMODEL);
    float rstd = rsqrtf(var + 1e-5f);
    #pragma unroll
    for (int j = 0; j < 8; j++) {
        int i = threadIdx.x + 256 * j;
        float val = (v[j] - mean) * rstd * w[i] + b[i];
        size_t idx = (size_t)row * DMODEL + i;
        if (outf) outf[idx] = val;
        if (outh) outh[idx] = __float2half(val);
    }
}

// ------------------------- sheaf (writes fp32 u + fp16) --------------------
__global__ void sheaf_kernel(const float* __restrict__ y,
                             const float* __restrict__ ctab,
                             const float* __restrict__ stab,
                             const float* __restrict__ alpha_p,
                             float* __restrict__ u,
                             __half* __restrict__ uh) {
    int row = blockIdx.x;
    int t = row & (TLEN - 1);
    float a = fabsf(alpha_p[0]);
    const float* yr = y + (size_t)row * DMODEL;
    #pragma unroll
    for (int jj = 0; jj < 4; jj++) {
        int p = threadIdx.x + 256 * jj;
        float r0 = yr[p], i0 = yr[p + DHALF];
        float lr = 4.f * r0, li = 4.f * i0;
        #pragma unroll
        for (int idx = 0; idx < 4; idx++) {
            int delta = idx - 3;
            float rs, is;
            if (delta == 0) { rs = r0; is = i0; }
            else if (t + delta >= 0) {
                const float* ys = y + (size_t)(row + delta) * DMODEL;
                rs = ys[p]; is = ys[p + DHALF];
            } else { rs = 0.f; is = 0.f; }
            float c = ctab[idx * DHALF + p], s = stab[idx * DHALF + p];
            lr -= c * rs + s * is;
            li -= c * is - s * rs;
        }
        float outr = r0 - a * lr, outi = i0 - a * li;
        size_t br = (size_t)row * DMODEL + p, bi = br + DHALF;
        u[br] = outr; u[bi] = outi;
        uh[br] = __float2half(outr);
        uh[bi] = __float2half(outi);
    }
}

// ------------------------- fused gist rotation block ------------------------
__global__ void gist_rot_kernel(const float* __restrict__ x1,
                                const float* __restrict__ lw, const float* __restrict__ lb,
                                const float* __restrict__ grw, const float* __restrict__ grb,
                                const float* __restrict__ gc, const float* __restrict__ gs,
                                float* __restrict__ x2) {
    int row = blockIdx.x;
    int b = row >> 11;
    const float* p = x1 + (size_t)row * DMODEL;
    float xr[4], xi[4];
    #pragma unroll
    for (int jj = 0; jj < 4; jj++) {
        int q = threadIdx.x + 256 * jj;
        xr[jj] = p[q]; xi[jj] = p[q + DHALF];
    }
    float s1 = 0.f;
    #pragma unroll
    for (int jj = 0; jj < 4; jj++) s1 += xr[jj] + xi[jj];
    float m1 = block_reduce_sum256(s1) * (1.f / DMODEL);
    float q1 = 0.f;
    #pragma unroll
    for (int jj = 0; jj < 4; jj++) {
        float dr = xr[jj] - m1, di = xi[jj] - m1;
        q1 += dr * dr + di * di;
    }
    float rstd1 = rsqrtf(block_reduce_sum256(q1) * (1.f / DMODEL) + 1e-5f);

    float xnr[4], xni[4], rr[4], ri[4];
    #pragma unroll
    for (int jj = 0; jj < 4; jj++) {
        int q = threadIdx.x + 256 * jj;
        xnr[jj] = (xr[jj] - m1) * rstd1 * lw[q] + lb[q];
        xni[jj] = (xi[jj] - m1) * rstd1 * lw[q + DHALF] + lb[q + DHALF];
        float c = gc[b * DHALF + q], sn = gs[b * DHALF + q];
        rr[jj] = xnr[jj] * c - xni[jj] * sn;
        ri[jj] = xnr[jj] * sn + xni[jj] * c;
    }
    float s2 = 0.f;
    #pragma unroll
    for (int jj = 0; jj < 4; jj++) s2 += rr[jj] + ri[jj];
    float m2 = block_reduce_sum256(s2) * (1.f / DMODEL);
    float q2 = 0.f;
    #pragma unroll
    for (int jj = 0; jj < 4; jj++) {
        float dr = rr[jj] - m2, di = ri[jj] - m2;
        q2 += dr * dr + di * di;
    }
    float rstd2 = rsqrtf(block_reduce_sum256(q2) * (1.f / DMODEL) + 1e-5f);

    #pragma unroll
    for (int jj = 0; jj < 4; jj++) {
        int q = threadIdx.x + 256 * jj;
        float outr = xr[jj] + (rr[jj] - m2) * rstd2 * grw[q] + grb[q] - xnr[jj];
        float outi = xi[jj] + (ri[jj] - m2) * rstd2 * grw[q + DHALF] + grb[q + DHALF] - xni[jj];
        x2[(size_t)row * DMODEL + q]         = outr;
        x2[(size_t)row * DMODEL + q + DHALF] = outi;
    }
}

// ------------------- split-K small GEMM (M=64, N=2048) ----------------------
#define SKC 64
__global__ __launch_bounds__(256, 4)
void smallgemm_kernel(const float* __restrict__ A, int lda,
                      const float* __restrict__ W, int ldw,
                      float* __restrict__ part, int Kdim) {
    __shared__ float Fs[64][SKC + 1];
    __shared__ float Ws[64][SKC + 1];
    const int n0 = blockIdx.x * 64;
    const int k0 = blockIdx.y * SKC;
    const int tid = threadIdx.x;

    for (int idx = tid; idx < 64 * SKC; idx += 256) {
        int r = idx >> 6, c = idx & 63;
        int k = k0 + c;
        Fs[r][c] = (k < Kdim) ? A[(size_t)r * lda + k] : 0.f;
        Ws[r][c] = (k < Kdim) ? W[(size_t)(n0 + r) * ldw + k] : 0.f;
    }
    __syncthreads();

    const int tx = tid & 15, ty = tid >> 4;
    float acc[4][4];
    #pragma unroll
    for (int i = 0; i < 4; i++)
        #pragma unroll
        for (int j = 0; j < 4; j++) acc[i][j] = 0.f;

    for (int k = 0; k < SKC; k++) {
        float ra[4], rb[4];
        #pragma unroll
        for (int i = 0; i < 4; i++) ra[i] = Fs[ty * 4 + i][k];
        #pragma unroll
        for (int j = 0; j < 4; j++) rb[j] = Ws[tx * 4 + j][k];
        #pragma unroll
        for (int i = 0; i < 4; i++)
            #pragma unroll
            for (int j = 0; j < 4; j++) acc[i][j] += ra[i] * rb[j];
    }

    float* pz = part + (size_t)blockIdx.y * (64 * DMODEL);
    #pragma unroll
    for (int i = 0; i < 4; i++)
        #pragma unroll
        for (int j = 0; j < 4; j++)
            pz[(size_t)(ty * 4 + i) * DMODEL + n0 + tx * 4 + j] = acc[i][j];
}

__global__ void skreduce_kernel(const float* __restrict__ part, int nparts,
                                const float* __restrict__ bias,
                                float* __restrict__ out) {
    int idx = blockIdx.x * 256 + threadIdx.x;
    if (idx >= 64 * DMODEL) return;
    float s = bias ? bias[idx & (DMODEL - 1)] : 0.f;
    for (int z = 0; z < nparts; z++) s += part[(size_t)z * (64 * DMODEL) + idx];
    out[idx] = s;
}

// ------------------------- fp16 HMMA single-term GEMM -----------------------
// D[m,n] = sum_k A16[m,k] * W16[n,k]
// CTA tile 128x256, BK=64, 8 warps as 2m x 4n, warp tile 64x64, ldmatrix,
// 3-stage cp.async pipeline.
#define GBK 64
#define ROWP 72
#define OFF_W     (128 * ROWP)                 // 9216 elements
#define STAGE_EL  (384 * ROWP)                 // 27648 elements
#define STAGE_B   (STAGE_EL * 2)               // 55296 bytes
#define NSTAGE 3
#define SMEM_GEMM (NSTAGE * STAGE_B)           // 165888 bytes

__global__ __launch_bounds__(256, 1)
void gemm_f16_kernel(const __half* __restrict__ A16,
                     const __half* __restrict__ W16,
                     float* __restrict__ D,
                     const float* __restrict__ add1,
                     const float* __restrict__ add2) {
    extern __shared__ __half sm[];
    const int tid  = threadIdx.x;
    const int lane = tid & 31;
    const int warp = tid >> 5;
    const int wm = warp & 1;            // 2 m-tiles of 64
    const int wn = warp >> 1;           // 4 n-tiles of 64
    const int m0 = blockIdx.y * 128, n0 = blockIdx.x * 256;
    const uint32_t smb = smem_u32(sm);

    float acc[4][8][4];
    #pragma unroll
    for (int mt = 0; mt < 4; mt++)
        #pragma unroll
        for (int nt = 0; nt < 8; nt++)
            #pragma unroll
            for (int j = 0; j < 4; j++) acc[mt][nt][j] = 0.f;

    const int NCHUNK = DMODEL / GBK;    // 32

    const int a_row = lane & 15;
    const int a_k8  = (lane >= 16) ? 8 : 0;
    const int b_row = (lane & 7) + ((lane >= 16) ? 8 : 0);
    const int b_k8  = ((lane >> 3) & 1) ? 8 : 0;

    auto issue_stage = [&](int kc, uint32_t sbase) {
        const int k0 = kc * GBK;
        #pragma unroll
        for (int i = 0; i < 4; i++) {                  // A: 1024 cp16
            int idx = tid + i * 256;
            int row = idx >> 3, ch = idx & 7;          // row 0..127
            cpasync16(sbase + (uint32_t)(row * ROWP + ch * 8) * 2,
                      A16 + (size_t)(m0 + row) * DMODEL + k0 + ch * 8);
        }
        #pragma unroll
        for (int i = 0; i < 8; i++) {                  // W: 2048 cp16
            int idx = tid + i * 256;
            int row = idx >> 3, ch = idx & 7;          // row 0..255
            cpasync16(sbase + (uint32_t)(OFF_W + row * ROWP + ch * 8) * 2,
                      W16 + (size_t)(n0 + row) * DMODEL + k0 + ch * 8);
        }
    };

    issue_stage(0, smb);
    CP_COMMIT();
    issue_stage(1, smb + STAGE_B);
    CP_COMMIT();

    for (int kc = 0; kc < NCHUNK; kc++) {
        if (kc + 2 < NCHUNK) {
            issue_stage(kc + 2, smb + ((kc + 2) % NSTAGE) * STAGE_B);
            CP_COMMIT();
            CP_WAIT(2);
        } else if (kc + 1 < NCHUNK) {
            CP_WAIT(1);
        } else {
            CP_WAIT(0);
        }
        __syncthreads();

        const uint32_t sbase = smb + (kc % NSTAGE) * STAGE_B;

        #pragma unroll
        for (int ks = 0; ks < 4; ks++) {
            const int kb = ks * 16;
            uint32_t ah[4][4];
            #pragma unroll
            for (int mt = 0; mt < 4; mt++) {
                int rowe = (wm * 64 + mt * 16 + a_row) * ROWP + kb + a_k8;
                ldsm_x4(ah[mt], sbase + (uint32_t)rowe * 2);
            }
            #pragma unroll
            for (int ntp = 0; ntp < 4; ntp++) {
                uint32_t bh[4];
                int rowe = OFF_W + (wn * 64 + ntp * 16 + b_row) * ROWP + kb + b_k8;
                ldsm_x4(bh, sbase + (uint32_t)rowe * 2);
                #pragma unroll
                for (int mt = 0; mt < 4; mt++) {
                    mma16816h(acc[mt][2 * ntp],     ah[mt], bh[0], bh[1]);
                    mma16816h(acc[mt][2 * ntp + 1], ah[mt], bh[2], bh[3]);
                }
            }
        }
        __syncthreads();
    }

    const int r  = lane >> 2;
    const int c2 = lane & 3;
    #pragma unroll
    for (int mt = 0; mt < 4; mt++) {
        #pragma unroll
        for (int nt = 0; nt < 8; nt++) {
            int row0 = m0 + wm * 64 + mt * 16 + r;
            int col  = n0 + wn * 64 + nt * 8 + c2 * 2;
            size_t i0 = (size_t)row0 * DMODEL + col;
            size_t i1 = i0 + (size_t)8 * DMODEL;
            float2 v0 = make_float2(acc[mt][nt][0], acc[mt][nt][1]);
            float2 v1 = make_float2(acc[mt][nt][2], acc[mt][nt][3]);
            if (add1) {
                float2 a0 = *(const float2*)(add1 + i0);
                float2 a1 = *(const float2*)(add1 + i1);
                v0.x += a0.x; v0.y += a0.y; v1.x += a1.x; v1.y += a1.y;
            }
            if (add2) {
                float2 a0 = *(const float2*)(add2 + i0);
                float2 a1 = *(const float2*)(add2 + i1);
                v0.x += a0.x; v0.y += a0.y; v1.x += a1.x; v1.y += a1.y;
            }
            *(float2*)(D + i0) = v0;
            *(float2*)(D + i1) = v1;
        }
    }
}

// ------------------------- gist cross-attention (16 kv tokens) ---------------
__global__ void attn_kernel(const float* __restrict__ Q,
                            const float* __restrict__ Kh,
                            const float* __restrict__ V,
                            __half* __restrict__ ch) {
    __shared__ float Ks[KGIST][HDIM];
    __shared__ float Vs[KGIST][HDIM];
    const int h = blockIdx.y, b = blockIdx.z;
    const int t0 = blockIdx.x * 32;
    for (int j = threadIdx.x; j < KGIST * HDIM; j += 256) {
        int k = j >> 7, c = j & 127;
        Ks[k][c] = Kh[(size_t)(b * KGIST + k) * DMODEL + h * HDIM + c];
        Vs[k][c] = V [(size_t)(b * KGIST + k) * DMODEL + h * HDIM + c];
    }
    __syncthreads();
    const int w = threadIdx.x >> 5, lane = threadIdx.x & 31;
    const float scale = 0.08838834764831845f;
    for (int it = 0; it < 4; it++) {
        int t = t0 + w * 4 + it;
        size_t base = ((size_t)(b * TLEN + t)) * DMODEL + h * HDIM + lane * 4;
        float q0 = Q[base], q1 = Q[base + 1], q2 = Q[base + 2], q3 = Q[base + 3];
        float sc[KGIST];
        #pragma unroll
        for (int k = 0; k < KGIST; k++) {
            float ps = q0 * Ks[k][lane * 4] + q1 * Ks[k][lane * 4 + 1]
                     + q2 * Ks[k][lane * 4 + 2] + q3 * Ks[k][lane * 4 + 3];
            #pragma unroll
            for (int o = 16; o > 0; o >>= 1) ps += __shfl_xor_sync(0xffffffffu, ps, o);
            sc[k] = ps * scale;
        }
        float mx = sc[0];
        #pragma unroll
        for (int k = 1; k < KGIST; k++) mx = fmaxf(mx, sc[k]);
        float ssum = 0.f;
        #pragma unroll
        for (int k = 0; k < KGIST; k++) { sc[k] = expf(sc[k] - mx); ssum += sc[k]; }
        float inv = 1.f / ssum;
        float c0 = 0.f, c1 = 0.f, c2 = 0.f, c3 = 0.f;
        #pragma unroll
        for (int k = 0; k < KGIST; k++) {
            float wk = sc[k] * inv;
            c0 += wk * Vs[k][lane * 4];
            c1 += wk * Vs[k][lane * 4 + 1];
            c2 += wk * Vs[k][lane * 4 + 2];
            c3 += wk * Vs[k][lane * 4 + 3];
        }
        ch[base]     = __float2half(c0);
        ch[base + 1] = __float2half(c1);
        ch[base + 2] = __float2half(c2);
        ch[base + 3] = __float2half(c3);
    }
}

// ------------------------- launcher -----------------------------------------
extern "C" void kernel_launch(void* const* d_in, const int* in_sizes, int n_in,
                              void* d_out, int out_size) {
    const float* x             = (const float*)d_in[0];
    const float* gist_theta    = (const float*)d_in[1];
    const float* gist_mag      = (const float*)d_in[2];
    const float* gist_weights  = (const float*)d_in[3];
    const float* ln_sheaf_w    = (const float*)d_in[4];
    const float* ln_sheaf_b    = (const float*)d_in[5];
    const float* sheaf_thetas  = (const float*)d_in[6];
    const float* alpha         = (const float*)d_in[7];
    const float* corr_W        = (const float*)d_in[8];
    const float* ln_gist_w     = (const float*)d_in[9];
    const float* ln_gist_b     = (const float*)d_in[10];
    const float* gist_strength = (const float*)d_in[11];
    const float* gr_ln_w       = (const float*)d_in[12];
    const float* gr_ln_b       = (const float*)d_in[13];
    const float* ln_gca_w      = (const float*)d_in[14];
    const float* ln_gca_b      = (const float*)d_in[15];
    const float* Wq            = (const float*)d_in[16];
    const float* Wk            = (const float*)d_in[17];
    const float* Wv            = (const float*)d_in[18];
    const float* Wo            = (const float*)d_in[19];
    const float* gist_up_W     = (const float*)d_in[20];
    const float* gist_up_b     = (const float*)d_in[21];
    float* out = (float*)d_out;

    float *y, *u, *x1, *x2, *q, *feat, *part, *repr, *kh, *v, *shc, *shs, *gc, *gs;
    __half *a16, *w16;
    cudaGetSymbolAddress((void**)&y,    g_y);
    cudaGetSymbolAddress((void**)&u,    g_u);
    cudaGetSymbolAddress((void**)&x1,   g_x1);
    cudaGetSymbolAddress((void**)&x2,   g_x2);
    cudaGetSymbolAddress((void**)&q,    g_q);
    cudaGetSymbolAddress((void**)&feat, g_feat);
    cudaGetSymbolAddress((void**)&part, g_part);
    cudaGetSymbolAddress((void**)&repr, g_repr);
    cudaGetSymbolAddress((void**)&kh,   g_kh);
    cudaGetSymbolAddress((void**)&v,    g_v);
    cudaGetSymbolAddress((void**)&shc,  g_shc);
    cudaGetSymbolAddress((void**)&shs,  g_shs);
    cudaGetSymbolAddress((void**)&gc,   g_gc);
    cudaGetSymbolAddress((void**)&gs,   g_gs);
    cudaGetSymbolAddress((void**)&a16,  g_a16);
    cudaGetSymbolAddress((void**)&w16,  g_w16);

    cudaFuncSetAttribute(gemm_f16_kernel,
                         cudaFuncAttributeMaxDynamicSharedMemorySize, SMEM_GEMM);

    dim3 ggemm(DMODEL / 256, NROWS / 128);   // (8, 64)
    const int wsplit4 = DMODEL * DMODEL / 4;
    const int kp_up = (KUP + SKC - 1) / SKC;       // 17
    const int kp_d  = DMODEL / SKC;                // 32
    const int redgrid = (64 * DMODEL + 255) / 256; // 512

    // prep
    prep_sheaf_cs_kernel<<<16, 256>>>(sheaf_thetas, shc, shs);
    gist_theta_kernel<<<BATCH, 256>>>(gist_theta, gist_mag, gist_weights, gist_strength, gc, gs);
    feat_kernel<<<BATCH * KGIST, 256>>>(gist_theta, gist_mag, feat);

    // gist K/V path: split-K small GEMMs (deterministic two-phase)
    smallgemm_kernel<<<dim3(32, kp_up), 256>>>(feat, KUP, gist_up_W, KUP, part, KUP);
    skreduce_kernel<<<redgrid, 256>>>(part, kp_up, gist_up_b, repr);
    smallgemm_kernel<<<dim3(32, kp_d), 256>>>(repr, DMODEL, Wk, DMODEL, part, DMODEL);
    skreduce_kernel<<<redgrid, 256>>>(part, kp_d, nullptr, kh);
    smallgemm_kernel<<<dim3(32, kp_d), 256>>>(repr, DMODEL, Wv, DMODEL, part, DMODEL);
    skreduce_kernel<<<redgrid, 256>>>(part, kp_d, nullptr, v);

    // stage 1: sheaf residual
    ln_kernel<<<NROWS, 256>>>(x, ln_sheaf_w, ln_sheaf_b, y, nullptr);
    sheaf_kernel<<<NROWS, 256>>>(y, shc, shs, alpha, u, a16);
    w16_kernel<<<(wsplit4 + 255) / 256, 256>>>(corr_W, w16, wsplit4);
    gemm_f16_kernel<<<ggemm, 256, SMEM_GEMM>>>(a16, w16, x1, x, u);

    // stage 2: gist rotation residual (fused)
    gist_rot_kernel<<<NROWS, 256>>>(x1, ln_gist_w, ln_gist_b, gr_ln_w, gr_ln_b, gc, gs, x2);

    // stage 3: gist cross-attention residual
    ln_kernel<<<NROWS, 256>>>(x2, ln_gca_w, ln_gca_b, nullptr, a16);
    w16_kernel<<<(wsplit4 + 255) / 256, 256>>>(Wq, w16, wsplit4);
    gemm_f16_kernel<<<ggemm, 256, SMEM_GEMM>>>(a16, w16, q, nullptr, nullptr);
    attn_kernel<<<dim3(TLEN / 32, NHEADS, BATCH), 256>>>(q, kh, v, a16);
    w16_kernel<<<(wsplit4 + 255) / 256, 256>>>(Wo, w16, wsplit4);
    gemm_f16_kernel<<<ggemm, 256, SMEM_GEMM>>>(a16, w16, out, x2, nullptr);

    (void)in_sizes; (void)n_in; (void)out_size;
}

// round 14
// speedup vs baseline: 1.9924x; 1.0252x over previous
#include <cuda_runtime.h>
#include <cuda_fp16.h>
#include <cuda.h>
#include <math.h>
#include <cstdint>

// Problem constants
#define BATCH 4
#define TLEN 2048
#define DMODEL 2048
#define DHALF 1024
#define NROWS (BATCH * TLEN)          // 8192
#define KGIST 16
#define NHEADS 16
#define HDIM 128
#define KUP 1025                       // gist_up feature dim (dh + 1)
#define MAXPART 32

// ------------------------- scratch (device globals; no allocation) ---------
__device__ float g_x1[NROWS * DMODEL];
__device__ float g_x2[NROWS * DMODEL];
__device__ __half g_a16[NROWS * DMODEL];
__device__ __half g_q16[NROWS * DMODEL];
__device__ __half g_w16[DMODEL * DMODEL];
__device__ float g_feat[BATCH * KGIST * KUP];
__device__ float g_part[MAXPART * 64 * 2 * DMODEL];          // split-K partials (33.5 MB)
__device__ float g_repr[BATCH * KGIST * DMODEL];
__device__ float g_kh  [BATCH * KGIST * DMODEL];
__device__ float g_v   [BATCH * KGIST * DMODEL];
__device__ float g_shc[4 * DHALF];
__device__ float g_shs[4 * DHALF];
__device__ float g_gc [BATCH * DHALF];
__device__ float g_gs [BATCH * DHALF];

// ------------------------- helpers -----------------------------------------
__device__ __forceinline__ uint32_t smem_u32(const void* p) {
    uint32_t a;
    asm("{ .reg .u64 t; cvta.to.shared.u64 t, %1; cvt.u32.u64 %0, t; }" : "=r"(a) : "l"(p));
    return a;
}

__device__ __forceinline__ void cpasync16(uint32_t dst, const void* src) {
    asm volatile("cp.async.cg.shared.global [%0], [%1], 16;" :: "r"(dst), "l"(src));
}
#define CP_COMMIT() asm volatile("cp.async.commit_group;" ::: "memory")
#define CP_WAIT(n)  asm volatile("cp.async.wait_group %0;" :: "n"(n) : "memory")

__device__ __forceinline__ float block_reduce_sum256(float v) {
    __shared__ float sb[8];
    int lane = threadIdx.x & 31, wid = threadIdx.x >> 5;
    #pragma unroll
    for (int o = 16; o > 0; o >>= 1) v += __shfl_xor_sync(0xffffffffu, v, o);
    if (lane == 0) sb[wid] = v;
    __syncthreads();
    float r = 0.f;
    #pragma unroll
    for (int i = 0; i < 8; i++) r += sb[i];
    __syncthreads();
    return r;
}

__device__ __forceinline__ void mma16816h(float* d, const uint32_t* a, uint32_t b0, uint32_t b1) {
    asm volatile(
        "mma.sync.aligned.m16n8k16.row.col.f32.f16.f16.f32 "
        "{%0,%1,%2,%3}, {%4,%5,%6,%7}, {%8,%9}, {%0,%1,%2,%3};"
        : "+f"(d[0]), "+f"(d[1]), "+f"(d[2]), "+f"(d[3])
        : "r"(a[0]), "r"(a[1]), "r"(a[2]), "r"(a[3]), "r"(b0), "r"(b1));
}

__device__ __forceinline__ void ldsm_x4(uint32_t* r, uint32_t addr) {
    asm volatile("ldmatrix.sync.aligned.m8n8.x4.shared.b16 {%0,%1,%2,%3}, [%4];"
                 : "=r"(r[0]), "=r"(r[1]), "=r"(r[2]), "=r"(r[3]) : "r"(addr));
}

// ------------------------- small prep kernels -------------------------------
__global__ void prep_sheaf_cs_kernel(const float* __restrict__ thetas,
                                     float* __restrict__ c, float* __restrict__ s) {
    int i = blockIdx.x * 256 + threadIdx.x;
    if (i < 4 * DHALF) { float th = thetas[i]; c[i] = cosf(th); s[i] = sinf(th); }
}

__global__ void gist_theta_kernel(const float* __restrict__ gtheta,
                                  const float* __restrict__ gmag,
                                  const float* __restrict__ gw,
                                  const float* __restrict__ gstrength,
                                  float* __restrict__ gc, float* __restrict__ gs) {
    int b = blockIdx.x;
    float wk[KGIST]; float wsum = 0.f;
    #pragma unroll
    for (int k = 0; k < KGIST; k++) { wk[k] = gw[b * KGIST + k] * gmag[b * KGIST + k]; wsum += wk[k]; }
    float inv = 1.f / (wsum + 1e-8f);
    float sig = 1.f / (1.f + expf(-gstrength[0]));
    for (int p = threadIdx.x; p < DHALF; p += 256) {
        float th = 0.f;
        #pragma unroll
        for (int k = 0; k < KGIST; k++) th += (wk[k] * inv) * gtheta[(size_t)(b * KGIST + k) * DHALF + p];
        th *= sig;
        gc[b * DHALF + p] = cosf(th);
        gs[b * DHALF + p] = sinf(th);
    }
}

__global__ void feat_kernel(const float* __restrict__ gtheta,
                            const float* __restrict__ gmag,
                            float* __restrict__ feat) {
    int r = blockIdx.x;           // 0..63
    for (int f = threadIdx.x; f < KUP; f += 256) {
        float v = (f < DHALF) ? gtheta[(size_t)r * DHALF + f] : gmag[r];
        feat[(size_t)r * KUP + f] = v;
    }
}

// fp32 -> fp16 weight conversion
__global__ void w16_kernel(const float* __restrict__ in,
                           __half* __restrict__ out, int n4) {
    int i = blockIdx.x * 256 + threadIdx.x;
    if (i >= n4) return;
    float4 v = ((const float4*)in)[i];
    ((__half2*)out)[2 * i]     = __floats2half2_rn(v.x, v.y);
    ((__half2*)out)[2 * i + 1] = __floats2half2_rn(v.z, v.w);
}

// ------------- fused LN_sheaf + sheaf (writes fp16 u only) ------------------
// u = y - |a|*lap,  y = LN(x) rowwise;  neighbor LN stats recomputed (L2-hot).
__global__ void sheaf_fused_kernel(const float* __restrict__ x,
                                   const float* __restrict__ lw,
                                   const float* __restrict__ lb,
                                   const float* __restrict__ ctab,
                                   const float* __restrict__ stab,
                                   const float* __restrict__ alpha_p,
                                   __half* __restrict__ uh) {
    int row = blockIdx.x;
    int t = row & (TLEN - 1);
    float a = fabsf(alpha_p[0]);

    float mean[4], rstd[4];
    #pragma unroll
    for (int idx = 0; idx < 4; idx++) {
        int delta = idx - 3;
        if (t + delta >= 0) {
            const float* p = x + (size_t)(row + delta) * DMODEL;
            float s = 0.f;
            #pragma unroll
            for (int j = 0; j < 8; j++) s += p[threadIdx.x + 256 * j];
            float m = block_reduce_sum256(s) * (1.f / DMODEL);
            float q = 0.f;
            #pragma unroll
            for (int j = 0; j < 8; j++) { float d = p[threadIdx.x + 256 * j] - m; q += d * d; }
            float var = block_reduce_sum256(q) * (1.f / DMODEL);
            mean[idx] = m; rstd[idx] = rsqrtf(var + 1e-5f);
        } else { mean[idx] = 0.f; rstd[idx] = 0.f; }
    }

    const float* xr = x + (size_t)row * DMODEL;
    const float m0v = mean[3], rs0 = rstd[3];
    #pragma unroll
    for (int jj = 0; jj < 4; jj++) {
        int p = threadIdx.x + 256 * jj;
        float wr = lw[p],        br_ = lb[p];
        float wi = lw[p + DHALF], bi_ = lb[p + DHALF];
        float r0 = (xr[p] - m0v) * rs0 * wr + br_;
        float i0 = (xr[p + DHALF] - m0v) * rs0 * wi + bi_;
        float lr = 4.f * r0, li = 4.f * i0;
        #pragma unroll
        for (int idx = 0; idx < 4; idx++) {
            int delta = idx - 3;
            float rs, is;
            if (delta == 0) { rs = r0; is = i0; }
            else if (t + delta >= 0) {
                const float* ys = x + (size_t)(row + delta) * DMODEL;
                rs = (ys[p] - mean[idx]) * rstd[idx] * wr + br_;
                is = (ys[p + DHALF] - mean[idx]) * rstd[idx] * wi + bi_;
            } else { rs = 0.f; is = 0.f; }
            float c = ctab[idx * DHALF + p], s = stab[idx * DHALF + p];
            lr -= c * rs + s * is;
            li -= c * is - s * rs;
        }
        size_t br = (size_t)row * DMODEL + p;
        uh[br]         = __float2half(r0 - a * lr);
        uh[br + DHALF] = __float2half(i0 - a * li);
    }
}

// ---------- fused gist rotation + LN_gca (writes x2 fp32 + a16 fp16) --------
__global__ void gist_rot_ln_kernel(const float* __restrict__ x1,
                                   const float* __restrict__ lw, const float* __restrict__ lb,
                                   const float* __restrict__ grw, const float* __restrict__ grb,
                                   const float* __restrict__ gc, const float* __restrict__ gs,
                                   const float* __restrict__ cw, const float* __restrict__ cb,
                                   float* __restrict__ x2,
                                   __half* __restrict__ a16) {
    int row = blockIdx.x;
    int b = row >> 11;
    const float* p = x1 + (size_t)row * DMODEL;
    float xr[4], xi[4];
    #pragma unroll
    for (int jj = 0; jj < 4; jj++) {
        int q = threadIdx.x + 256 * jj;
        xr[jj] = p[q]; xi[jj] = p[q + DHALF];
    }
    float s1 = 0.f;
    #pragma unroll
    for (int jj = 0; jj < 4; jj++) s1 += xr[jj] + xi[jj];
    float m1 = block_reduce_sum256(s1) * (1.f / DMODEL);
    float q1 = 0.f;
    #pragma unroll
    for (int jj = 0; jj < 4; jj++) {
        float dr = xr[jj] - m1, di = xi[jj] - m1;
        q1 += dr * dr + di * di;
    }
    float rstd1 = rsqrtf(block_reduce_sum256(q1) * (1.f / DMODEL) + 1e-5f);

    float xnr[4], xni[4], rr[4], ri[4];
    #pragma unroll
    for (int jj = 0; jj < 4; jj++) {
        int q = threadIdx.x + 256 * jj;
        xnr[jj] = (xr[jj] - m1) * rstd1 * lw[q] + lb[q];
        xni[jj] = (xi[jj] - m1) * rstd1 * lw[q + DHALF] + lb[q + DHALF];
        float c = gc[b * DHALF + q], sn = gs[b * DHALF + q];
        rr[jj] = xnr[jj] * c - xni[jj] * sn;
        ri[jj] = xnr[jj] * sn + xni[jj] * c;
    }
    float s2 = 0.f;
    #pragma unroll
    for (int jj = 0; jj < 4; jj++) s2 += rr[jj] + ri[jj];
    float m2 = block_reduce_sum256(s2) * (1.f / DMODEL);
    float q2 = 0.f;
    #pragma unroll
    for (int jj = 0; jj < 4; jj++) {
        float dr = rr[jj] - m2, di = ri[jj] - m2;
        q2 += dr * dr + di * di;
    }
    float rstd2 = rsqrtf(block_reduce_sum256(q2) * (1.f / DMODEL) + 1e-5f);

    // x2 values in registers
    float o_r[4], o_i[4];
    #pragma unroll
    for (int jj = 0; jj < 4; jj++) {
        int q = threadIdx.x + 256 * jj;
        o_r[jj] = xr[jj] + (rr[jj] - m2) * rstd2 * grw[q] + grb[q] - xnr[jj];
        o_i[jj] = xi[jj] + (ri[jj] - m2) * rstd2 * grw[q + DHALF] + grb[q + DHALF] - xni[jj];
    }

    // third LN (ln_gca) over x2
    float s3 = 0.f;
    #pragma unroll
    for (int jj = 0; jj < 4; jj++) s3 += o_r[jj] + o_i[jj];
    float m3 = block_reduce_sum256(s3) * (1.f / DMODEL);
    float q3 = 0.f;
    #pragma unroll
    for (int jj = 0; jj < 4; jj++) {
        float dr = o_r[jj] - m3, di = o_i[jj] - m3;
        q3 += dr * dr + di * di;
    }
    float rstd3 = rsqrtf(block_reduce_sum256(q3) * (1.f / DMODEL) + 1e-5f);

    #pragma unroll
    for (int jj = 0; jj < 4; jj++) {
        int q = threadIdx.x + 256 * jj;
        size_t ir = (size_t)row * DMODEL + q, ii = ir + DHALF;
        x2[ir] = o_r[jj];
        x2[ii] = o_i[jj];
        a16[ir] = __float2half((o_r[jj] - m3) * rstd3 * cw[q] + cb[q]);
        a16[ii] = __float2half((o_i[jj] - m3) * rstd3 * cw[q + DHALF] + cb[q + DHALF]);
    }
}

// ------------------- split-K small GEMMs (M=64) -----------------------------
#define SKC 64
__global__ __launch_bounds__(256, 4)
void smallgemm_kernel(const float* __restrict__ A, int lda,
                      const float* __restrict__ W, int ldw,
                      float* __restrict__ part, int Kdim) {
    __shared__ float Fs[64][SKC + 1];
    __shared__ float Ws[64][SKC + 1];
    const int n0 = blockIdx.x * 64;
    const int k0 = blockIdx.y * SKC;
    const int tid = threadIdx.x;

    for (int idx = tid; idx < 64 * SKC; idx += 256) {
        int r = idx >> 6, c = idx & 63;
        int k = k0 + c;
        Fs[r][c] = (k < Kdim) ? A[(size_t)r * lda + k] : 0.f;
        Ws[r][c] = (k < Kdim) ? W[(size_t)(n0 + r) * ldw + k] : 0.f;
    }
    __syncthreads();

    const int tx = tid & 15, ty = tid >> 4;
    float acc[4][4];
    #pragma unroll
    for (int i = 0; i < 4; i++)
        #pragma unroll
        for (int j = 0; j < 4; j++) acc[i][j] = 0.f;

    for (int k = 0; k < SKC; k++) {
        float ra[4], rb[4];
        #pragma unroll
        for (int i = 0; i < 4; i++) ra[i] = Fs[ty * 4 + i][k];
        #pragma unroll
        for (int j = 0; j < 4; j++) rb[j] = Ws[tx * 4 + j][k];
        #pragma unroll
        for (int i = 0; i < 4; i++)
            #pragma unroll
            for (int j = 0; j < 4; j++) acc[i][j] += ra[i] * rb[j];
    }

    float* pz = part + (size_t)blockIdx.y * (64 * DMODEL);
    #pragma unroll
    for (int i = 0; i < 4; i++)
        #pragma unroll
        for (int j = 0; j < 4; j++)
            pz[(size_t)(ty * 4 + i) * DMODEL + n0 + tx * 4 + j] = acc[i][j];
}

__global__ void skreduce_kernel(const float* __restrict__ part, int nparts,
                                const float* __restrict__ bias,
                                float* __restrict__ out) {
    int idx = blockIdx.x * 256 + threadIdx.x;
    if (idx >= 64 * DMODEL) return;
    float s = bias ? bias[idx & (DMODEL - 1)] : 0.f;
    for (int z = 0; z < nparts; z++) s += part[(size_t)z * (64 * DMODEL) + idx];
    out[idx] = s;
}

// Combined K+V small GEMM: N = 4096 (Wk cols then Wv cols)
__global__ __launch_bounds__(256, 4)
void smallgemm_kv_kernel(const float* __restrict__ A,
                         const float* __restrict__ Wk,
                         const float* __restrict__ Wv,
                         float* __restrict__ part) {
    __shared__ float Fs[64][SKC + 1];
    __shared__ float Ws[64][SKC + 1];
    const int n0g = blockIdx.x * 64;     // 0..4032
    const float* W = (n0g < DMODEL) ? Wk + (size_t)n0g * DMODEL
                                    : Wv + (size_t)(n0g - DMODEL) * DMODEL;
    const int k0 = blockIdx.y * SKC;
    const int tid = threadIdx.x;

    for (int idx = tid; idx < 64 * SKC; idx += 256) {
        int r = idx >> 6, c = idx & 63;
        Fs[r][c] = A[(size_t)r * DMODEL + k0 + c];
        Ws[r][c] = W[(size_t)r * DMODEL + k0 + c];
    }
    __syncthreads();

    const int tx = tid & 15, ty = tid >> 4;
    float acc[4][4];
    #pragma unroll
    for (int i = 0; i < 4; i++)
        #pragma unroll
        for (int j = 0; j < 4; j++) acc[i][j] = 0.f;

    for (int k = 0; k < SKC; k++) {
        float ra[4], rb[4];
        #pragma unroll
        for (int i = 0; i < 4; i++) ra[i] = Fs[ty * 4 + i][k];
        #pragma unroll
        for (int j = 0; j < 4; j++) rb[j] = Ws[tx * 4 + j][k];
        #pragma unroll
        for (int i = 0; i < 4; i++)
            #pragma unroll
            for (int j = 0; j < 4; j++) acc[i][j] += ra[i] * rb[j];
    }

    float* pz = part + (size_t)blockIdx.y * (64 * 2 * DMODEL);
    #pragma unroll
    for (int i = 0; i < 4; i++)
        #pragma unroll
        for (int j = 0; j < 4; j++)
            pz[(size_t)(ty * 4 + i) * (2 * DMODEL) + n0g + tx * 4 + j] = acc[i][j];
}

__global__ void skreduce_kv_kernel(const float* __restrict__ part, int nparts,
                                   float* __restrict__ kh, float* __restrict__ v) {
    int idx = blockIdx.x * 256 + threadIdx.x;      // 0 .. 64*4096-1
    if (idx >= 64 * 2 * DMODEL) return;
    float s = 0.f;
    for (int z = 0; z < nparts; z++) s += part[(size_t)z * (64 * 2 * DMODEL) + idx];
    int m = idx >> 12, n = idx & (2 * DMODEL - 1);
    if (n < DMODEL) kh[(size_t)m * DMODEL + n] = s;
    else            v [(size_t)m * DMODEL + (n - DMODEL)] = s;
}

// ------------------------- fp16 HMMA single-term GEMM -----------------------
// D[m,n] = sum_k A16[m,k] * W16[n,k] (+ add1 fp32) (+ addh fp16); out fp32 or fp16
#define GBK 64
#define ROWP 72
#define OFF_W     (128 * ROWP)
#define STAGE_EL  (384 * ROWP)
#define STAGE_B   (STAGE_EL * 2)
#define NSTAGE 3
#define SMEM_GEMM (NSTAGE * STAGE_B)           // 165888 bytes

__global__ __launch_bounds__(256, 1)
void gemm_f16_kernel(const __half* __restrict__ A16,
                     const __half* __restrict__ W16,
                     float* __restrict__ D,
                     __half* __restrict__ Dh,
                     const float* __restrict__ add1,
                     const __half* __restrict__ addh) {
    extern __shared__ __half sm[];
    const int tid  = threadIdx.x;
    const int lane = tid & 31;
    const int warp = tid >> 5;
    const int wm = warp & 1;
    const int wn = warp >> 1;
    const int m0 = blockIdx.y * 128, n0 = blockIdx.x * 256;
    const uint32_t smb = smem_u32(sm);

    float acc[4][8][4];
    #pragma unroll
    for (int mt = 0; mt < 4; mt++)
        #pragma unroll
        for (int nt = 0; nt < 8; nt++)
            #pragma unroll
            for (int j = 0; j < 4; j++) acc[mt][nt][j] = 0.f;

    const int NCHUNK = DMODEL / GBK;    // 32

    const int a_row = lane & 15;
    const int a_k8  = (lane >= 16) ? 8 : 0;
    const int b_row = (lane & 7) + ((lane >= 16) ? 8 : 0);
    const int b_k8  = ((lane >> 3) & 1) ? 8 : 0;

    auto issue_stage = [&](int kc, uint32_t sbase) {
        const int k0 = kc * GBK;
        #pragma unroll
        for (int i = 0; i < 4; i++) {
            int idx = tid + i * 256;
            int row = idx >> 3, ch = idx & 7;
            cpasync16(sbase + (uint32_t)(row * ROWP + ch * 8) * 2,
                      A16 + (size_t)(m0 + row) * DMODEL + k0 + ch * 8);
        }
        #pragma unroll
        for (int i = 0; i < 8; i++) {
            int idx = tid + i * 256;
            int row = idx >> 3, ch = idx & 7;
            cpasync16(sbase + (uint32_t)(OFF_W + row * ROWP + ch * 8) * 2,
                      W16 + (size_t)(n0 + row) * DMODEL + k0 + ch * 8);
        }
    };

    issue_stage(0, smb);
    CP_COMMIT();
    issue_stage(1, smb + STAGE_B);
    CP_COMMIT();

    for (int kc = 0; kc < NCHUNK; kc++) {
        if (kc + 2 < NCHUNK) {
            issue_stage(kc + 2, smb + ((kc + 2) % NSTAGE) * STAGE_B);
            CP_COMMIT();
            CP_WAIT(2);
        } else if (kc + 1 < NCHUNK) {
            CP_WAIT(1);
        } else {
            CP_WAIT(0);
        }
        __syncthreads();

        const uint32_t sbase = smb + (kc % NSTAGE) * STAGE_B;

        #pragma unroll
        for (int ks = 0; ks < 4; ks++) {
            const int kb = ks * 16;
            uint32_t ah[4][4];
            #pragma unroll
            for (int mt = 0; mt < 4; mt++) {
                int rowe = (wm * 64 + mt * 16 + a_row) * ROWP + kb + a_k8;
                ldsm_x4(ah[mt], sbase + (uint32_t)rowe * 2);
            }
            #pragma unroll
            for (int ntp = 0; ntp < 4; ntp++) {
                uint32_t bh[4];
                int rowe = OFF_W + (wn * 64 + ntp * 16 + b_row) * ROWP + kb + b_k8;
                ldsm_x4(bh, sbase + (uint32_t)rowe * 2);
                #pragma unroll
                for (int mt = 0; mt < 4; mt++) {
                    mma16816h(acc[mt][2 * ntp],     ah[mt], bh[0], bh[1]);
                    mma16816h(acc[mt][2 * ntp + 1], ah[mt], bh[2], bh[3]);
                }
            }
        }
        __syncthreads();
    }

    const int r  = lane >> 2;
    const int c2 = lane & 3;
    #pragma unroll
    for (int mt = 0; mt < 4; mt++) {
        #pragma unroll
        for (int nt = 0; nt < 8; nt++) {
            int row0 = m0 + wm * 64 + mt * 16 + r;
            int col  = n0 + wn * 64 + nt * 8 + c2 * 2;
            size_t i0 = (size_t)row0 * DMODEL + col;
            size_t i1 = i0 + (size_t)8 * DMODEL;
            float2 v0 = make_float2(acc[mt][nt][0], acc[mt][nt][1]);
            float2 v1 = make_float2(acc[mt][nt][2], acc[mt][nt][3]);
            if (add1) {
                float2 a0 = *(const float2*)(add1 + i0);
                float2 a1 = *(const float2*)(add1 + i1);
                v0.x += a0.x; v0.y += a0.y; v1.x += a1.x; v1.y += a1.y;
            }
            if (addh) {
                __half2 h0 = *(const __half2*)(addh + i0);
                __half2 h1 = *(const __half2*)(addh + i1);
                float2 f0 = __half22float2(h0), f1 = __half22float2(h1);
                v0.x += f0.x; v0.y += f0.y; v1.x += f1.x; v1.y += f1.y;
            }
            if (D) {
                *(float2*)(D + i0) = v0;
                *(float2*)(D + i1) = v1;
            }
            if (Dh) {
                *(__half2*)(Dh + i0) = __floats2half2_rn(v0.x, v0.y);
                *(__half2*)(Dh + i1) = __floats2half2_rn(v1.x, v1.y);
            }
        }
    }
}

// ------------------------- gist cross-attention (16 kv tokens) ---------------
__global__ void attn_kernel(const __half* __restrict__ Q,
                            const float* __restrict__ Kh,
                            const float* __restrict__ V,
                            __half* __restrict__ ch) {
    __shared__ float Ks[KGIST][HDIM];
    __shared__ float Vs[KGIST][HDIM];
    const int h = blockIdx.y, b = blockIdx.z;
    const int t0 = blockIdx.x * 32;
    for (int j = threadIdx.x; j < KGIST * HDIM; j += 256) {
        int k = j >> 7, c = j & 127;
        Ks[k][c] = Kh[(size_t)(b * KGIST + k) * DMODEL + h * HDIM + c];
        Vs[k][c] = V [(size_t)(b * KGIST + k) * DMODEL + h * HDIM + c];
    }
    __syncthreads();
    const int w = threadIdx.x >> 5, lane = threadIdx.x & 31;
    const float scale = 0.08838834764831845f;
    for (int it = 0; it < 4; it++) {
        int t = t0 + w * 4 + it;
        size_t base = ((size_t)(b * TLEN + t)) * DMODEL + h * HDIM + lane * 4;
        __half2 qh0 = *(const __half2*)(Q + base);
        __half2 qh1 = *(const __half2*)(Q + base + 2);
        float2 qf0 = __half22float2(qh0), qf1 = __half22float2(qh1);
        float q0 = qf0.x, q1 = qf0.y, q2 = qf1.x, q3 = qf1.y;
        float sc[KGIST];
        #pragma unroll
        for (int k = 0; k < KGIST; k++) {
            float ps = q0 * Ks[k][lane * 4] + q1 * Ks[k][lane * 4 + 1]
                     + q2 * Ks[k][lane * 4 + 2] + q3 * Ks[k][lane * 4 + 3];
            #pragma unroll
            for (int o = 16; o > 0; o >>= 1) ps += __shfl_xor_sync(0xffffffffu, ps, o);
            sc[k] = ps * scale;
        }
        float mx = sc[0];
        #pragma unroll
        for (int k = 1; k < KGIST; k++) mx = fmaxf(mx, sc[k]);
        float ssum = 0.f;
        #pragma unroll
        for (int k = 0; k < KGIST; k++) { sc[k] = expf(sc[k] - mx); ssum += sc[k]; }
        float inv = 1.f / ssum;
        float c0 = 0.f, c1 = 0.f, c2 = 0.f, c3 = 0.f;
        #pragma unroll
        for (int k = 0; k < KGIST; k++) {
            float wk = sc[k] * inv;
            c0 += wk * Vs[k][lane * 4];
            c1 += wk * Vs[k][lane * 4 + 1];
            c2 += wk * Vs[k][lane * 4 + 2];
            c3 += wk * Vs[k][lane * 4 + 3];
        }
        *(__half2*)(ch + base)     = __floats2half2_rn(c0, c1);
        *(__half2*)(ch + base + 2) = __floats2half2_rn(c2, c3);
    }
}

// ------------------------- launcher -----------------------------------------
extern "C" void kernel_launch(void* const* d_in, const int* in_sizes, int n_in,
                              void* d_out, int out_size) {
    const float* x             = (const float*)d_in[0];
    const float* gist_theta    = (const float*)d_in[1];
    const float* gist_mag      = (const float*)d_in[2];
    const float* gist_weights  = (const float*)d_in[3];
    const float* ln_sheaf_w    = (const float*)d_in[4];
    const float* ln_sheaf_b    = (const float*)d_in[5];
    const float* sheaf_thetas  = (const float*)d_in[6];
    const float* alpha         = (const float*)d_in[7];
    const float* corr_W        = (const float*)d_in[8];
    const float* ln_gist_w     = (const float*)d_in[9];
    const float* ln_gist_b     = (const float*)d_in[10];
    const float* gist_strength = (const float*)d_in[11];
    const float* gr_ln_w       = (const float*)d_in[12];
    const float* gr_ln_b       = (const float*)d_in[13];
    const float* ln_gca_w      = (const float*)d_in[14];
    const float* ln_gca_b      = (const float*)d_in[15];
    const float* Wq            = (const float*)d_in[16];
    const float* Wk            = (const float*)d_in[17];
    const float* Wv            = (const float*)d_in[18];
    const float* Wo            = (const float*)d_in[19];
    const float* gist_up_W     = (const float*)d_in[20];
    const float* gist_up_b     = (const float*)d_in[21];
    float* out = (float*)d_out;

    float *x1, *x2, *feat, *part, *repr, *kh, *v, *shc, *shs, *gc, *gs;
    __half *a16, *q16, *w16;
    cudaGetSymbolAddress((void**)&x1,   g_x1);
    cudaGetSymbolAddress((void**)&x2,   g_x2);
    cudaGetSymbolAddress((void**)&feat, g_feat);
    cudaGetSymbolAddress((void**)&part, g_part);
    cudaGetSymbolAddress((void**)&repr, g_repr);
    cudaGetSymbolAddress((void**)&kh,   g_kh);
    cudaGetSymbolAddress((void**)&v,    g_v);
    cudaGetSymbolAddress((void**)&shc,  g_shc);
    cudaGetSymbolAddress((void**)&shs,  g_shs);
    cudaGetSymbolAddress((void**)&gc,   g_gc);
    cudaGetSymbolAddress((void**)&gs,   g_gs);
    cudaGetSymbolAddress((void**)&a16,  g_a16);
    cudaGetSymbolAddress((void**)&q16,  g_q16);
    cudaGetSymbolAddress((void**)&w16,  g_w16);

    cudaFuncSetAttribute(gemm_f16_kernel,
                         cudaFuncAttributeMaxDynamicSharedMemorySize, SMEM_GEMM);

    dim3 ggemm(DMODEL / 256, NROWS / 128);   // (8, 64)
    const int wsplit4 = DMODEL * DMODEL / 4;
    const int kp_up = (KUP + SKC - 1) / SKC;       // 17
    const int kp_d  = DMODEL / SKC;                // 32
    const int redgrid   = (64 * DMODEL + 255) / 256;     // 512
    const int redgridkv = (64 * 2 * DMODEL + 255) / 256; // 1024

    // prep
    prep_sheaf_cs_kernel<<<16, 256>>>(sheaf_thetas, shc, shs);
    gist_theta_kernel<<<BATCH, 256>>>(gist_theta, gist_mag, gist_weights, gist_strength, gc, gs);
    feat_kernel<<<BATCH * KGIST, 256>>>(gist_theta, gist_mag, feat);

    // gist K/V path
    smallgemm_kernel<<<dim3(32, kp_up), 256>>>(feat, KUP, gist_up_W, KUP, part, KUP);
    skreduce_kernel<<<redgrid, 256>>>(part, kp_up, gist_up_b, repr);
    smallgemm_kv_kernel<<<dim3(64, kp_d), 256>>>(repr, Wk, Wv, part);
    skreduce_kv_kernel<<<redgridkv, 256>>>(part, kp_d, kh, v);

    // stage 1: sheaf residual (fused LN + sheaf, fp16 u only)
    sheaf_fused_kernel<<<NROWS, 256>>>(x, ln_sheaf_w, ln_sheaf_b, shc, shs, alpha, a16);
    w16_kernel<<<(wsplit4 + 255) / 256, 256>>>(corr_W, w16, wsplit4);
    gemm_f16_kernel<<<ggemm, 256, SMEM_GEMM>>>(a16, w16, x1, nullptr, x, a16);

    // stage 2: gist rotation residual + LN_gca (fused)
    gist_rot_ln_kernel<<<NROWS, 256>>>(x1, ln_gist_w, ln_gist_b, gr_ln_w, gr_ln_b,
                                       gc, gs, ln_gca_w, ln_gca_b, x2, a16);

    // stage 3: gist cross-attention residual
    w16_kernel<<<(wsplit4 + 255) / 256, 256>>>(Wq, w16, wsplit4);
    gemm_f16_kernel<<<ggemm, 256, SMEM_GEMM>>>(a16, w16, nullptr, q16, nullptr, nullptr);
    attn_kernel<<<dim3(TLEN / 32, NHEADS, BATCH), 256>>>(q16, kh, v, a16);
    w16_kernel<<<(wsplit4 + 255) / 256, 256>>>(Wo, w16, wsplit4);
    gemm_f16_kernel<<<ggemm, 256, SMEM_GEMM>>>(a16, w16, out, nullptr, x2, nullptr);

    (void)in_sizes; (void)n_in; (void)out_size;
}

// round 15
// speedup vs baseline: 2.0994x; 1.0537x over previous
#include <cuda_runtime.h>
#include <cuda_fp16.h>
#include <cuda.h>
#include <math.h>
#include <cstdint>

// Problem constants
#define BATCH 4
#define TLEN 2048
#define DMODEL 2048
#define DHALF 1024
#define NROWS (BATCH * TLEN)          // 8192
#define KGIST 16
#define NHEADS 16
#define HDIM 128
#define KUP 1025
#define MAXPART 32

// ------------------------- scratch (device globals; no allocation) ---------
__device__ __half g_x1h[NROWS * DMODEL];
__device__ __half g_x2h[NROWS * DMODEL];
__device__ __half g_a16[NROWS * DMODEL];
__device__ __half g_q16[NROWS * DMODEL];
__device__ __half g_w16a[DMODEL * DMODEL];
__device__ __half g_w16b[DMODEL * DMODEL];
__device__ __half g_w16c[DMODEL * DMODEL];
__device__ float2 g_stats[NROWS];
__device__ float g_feat[BATCH * KGIST * KUP];
__device__ float g_part[MAXPART * 64 * 2 * DMODEL];
__device__ float g_repr[BATCH * KGIST * DMODEL];
__device__ float g_kh  [BATCH * KGIST * DMODEL];
__device__ float g_v   [BATCH * KGIST * DMODEL];
__device__ float g_shc[4 * DHALF];
__device__ float g_shs[4 * DHALF];
__device__ float g_gc [BATCH * DHALF];
__device__ float g_gs [BATCH * DHALF];

// ------------------------- helpers -----------------------------------------
__device__ __forceinline__ uint32_t smem_u32(const void* p) {
    uint32_t a;
    asm("{ .reg .u64 t; cvta.to.shared.u64 t, %1; cvt.u32.u64 %0, t; }" : "=r"(a) : "l"(p));
    return a;
}

__device__ __forceinline__ void cpasync16(uint32_t dst, const void* src) {
    asm volatile("cp.async.cg.shared.global [%0], [%1], 16;" :: "r"(dst), "l"(src));
}
#define CP_COMMIT() asm volatile("cp.async.commit_group;" ::: "memory")
#define CP_WAIT(n)  asm volatile("cp.async.wait_group %0;" :: "n"(n) : "memory")

__device__ __forceinline__ float block_reduce_sum256(float v) {
    __shared__ float sb[8];
    int lane = threadIdx.x & 31, wid = threadIdx.x >> 5;
    #pragma unroll
    for (int o = 16; o > 0; o >>= 1) v += __shfl_xor_sync(0xffffffffu, v, o);
    if (lane == 0) sb[wid] = v;
    __syncthreads();
    float r = 0.f;
    #pragma unroll
    for (int i = 0; i < 8; i++) r += sb[i];
    __syncthreads();
    return r;
}

__device__ __forceinline__ void mma16816h(float* d, const uint32_t* a, uint32_t b0, uint32_t b1) {
    asm volatile(
        "mma.sync.aligned.m16n8k16.row.col.f32.f16.f16.f32 "
        "{%0,%1,%2,%3}, {%4,%5,%6,%7}, {%8,%9}, {%0,%1,%2,%3};"
        : "+f"(d[0]), "+f"(d[1]), "+f"(d[2]), "+f"(d[3])
        : "r"(a[0]), "r"(a[1]), "r"(a[2]), "r"(a[3]), "r"(b0), "r"(b1));
}

__device__ __forceinline__ void ldsm_x4(uint32_t* r, uint32_t addr) {
    asm volatile("ldmatrix.sync.aligned.m8n8.x4.shared.b16 {%0,%1,%2,%3}, [%4];"
                 : "=r"(r[0]), "=r"(r[1]), "=r"(r[2]), "=r"(r[3]) : "r"(addr));
}

// ------------------------- small prep kernels -------------------------------
__global__ void prep_sheaf_cs_kernel(const float* __restrict__ thetas,
                                     float* __restrict__ c, float* __restrict__ s) {
    int i = blockIdx.x * 256 + threadIdx.x;
    if (i < 4 * DHALF) { float th = thetas[i]; c[i] = cosf(th); s[i] = sinf(th); }
}

__global__ void gist_theta_kernel(const float* __restrict__ gtheta,
                                  const float* __restrict__ gmag,
                                  const float* __restrict__ gw,
                                  const float* __restrict__ gstrength,
                                  float* __restrict__ gc, float* __restrict__ gs) {
    int b = blockIdx.x;
    float wk[KGIST]; float wsum = 0.f;
    #pragma unroll
    for (int k = 0; k < KGIST; k++) { wk[k] = gw[b * KGIST + k] * gmag[b * KGIST + k]; wsum += wk[k]; }
    float inv = 1.f / (wsum + 1e-8f);
    float sig = 1.f / (1.f + expf(-gstrength[0]));
    for (int p = threadIdx.x; p < DHALF; p += 256) {
        float th = 0.f;
        #pragma unroll
        for (int k = 0; k < KGIST; k++) th += (wk[k] * inv) * gtheta[(size_t)(b * KGIST + k) * DHALF + p];
        th *= sig;
        gc[b * DHALF + p] = cosf(th);
        gs[b * DHALF + p] = sinf(th);
    }
}

__global__ void feat_kernel(const float* __restrict__ gtheta,
                            const float* __restrict__ gmag,
                            float* __restrict__ feat) {
    int r = blockIdx.x;
    for (int f = threadIdx.x; f < KUP; f += 256) {
        float v = (f < DHALF) ? gtheta[(size_t)r * DHALF + f] : gmag[r];
        feat[(size_t)r * KUP + f] = v;
    }
}

// fp32 -> fp16 weight conversion
__global__ void w16_kernel(const float* __restrict__ in,
                           __half* __restrict__ out, int n4) {
    int i = blockIdx.x * 256 + threadIdx.x;
    if (i >= n4) return;
    float4 v = ((const float4*)in)[i];
    ((__half2*)out)[2 * i]     = __floats2half2_rn(v.x, v.y);
    ((__half2*)out)[2 * i + 1] = __floats2half2_rn(v.z, v.w);
}

// ------------------------- row LN stats -------------------------------------
__global__ void rowstats_kernel(const float* __restrict__ x,
                                float2* __restrict__ stats) {
    int row = blockIdx.x;
    const float* p = x + (size_t)row * DMODEL;
    float v[8];
    #pragma unroll
    for (int j = 0; j < 8; j++) v[j] = p[threadIdx.x + 256 * j];
    float s = 0.f;
    #pragma unroll
    for (int j = 0; j < 8; j++) s += v[j];
    float mean = block_reduce_sum256(s) * (1.f / DMODEL);
    float q = 0.f;
    #pragma unroll
    for (int j = 0; j < 8; j++) { float d = v[j] - mean; q += d * d; }
    float var = block_reduce_sum256(q) * (1.f / DMODEL);
    if (threadIdx.x == 0) stats[row] = make_float2(mean, rsqrtf(var + 1e-5f));
}

// ------------- sheaf apply (uses precomputed stats; writes fp16 u) ----------
__global__ void sheaf_apply_kernel(const float* __restrict__ x,
                                   const float* __restrict__ lw,
                                   const float* __restrict__ lb,
                                   const float* __restrict__ ctab,
                                   const float* __restrict__ stab,
                                   const float* __restrict__ alpha_p,
                                   const float2* __restrict__ stats,
                                   __half* __restrict__ uh) {
    int row = blockIdx.x;
    int t = row & (TLEN - 1);
    float a = fabsf(alpha_p[0]);

    float mean[4], rstd[4];
    #pragma unroll
    for (int idx = 0; idx < 4; idx++) {
        int delta = idx - 3;
        if (t + delta >= 0) {
            float2 st = stats[row + delta];
            mean[idx] = st.x; rstd[idx] = st.y;
        } else { mean[idx] = 0.f; rstd[idx] = 0.f; }
    }

    const float* xr = x + (size_t)row * DMODEL;
    const float m0v = mean[3], rs0 = rstd[3];
    #pragma unroll
    for (int jj = 0; jj < 4; jj++) {
        int p = threadIdx.x + 256 * jj;
        float wr = lw[p],         br_ = lb[p];
        float wi = lw[p + DHALF], bi_ = lb[p + DHALF];
        float r0 = (xr[p] - m0v) * rs0 * wr + br_;
        float i0 = (xr[p + DHALF] - m0v) * rs0 * wi + bi_;
        float lr = 4.f * r0, li = 4.f * i0;
        #pragma unroll
        for (int idx = 0; idx < 4; idx++) {
            int delta = idx - 3;
            float rs, is;
            if (delta == 0) { rs = r0; is = i0; }
            else if (t + delta >= 0) {
                const float* ys = x + (size_t)(row + delta) * DMODEL;
                rs = (ys[p] - mean[idx]) * rstd[idx] * wr + br_;
                is = (ys[p + DHALF] - mean[idx]) * rstd[idx] * wi + bi_;
            } else { rs = 0.f; is = 0.f; }
            float c = ctab[idx * DHALF + p], s = stab[idx * DHALF + p];
            lr -= c * rs + s * is;
            li -= c * is - s * rs;
        }
        size_t br = (size_t)row * DMODEL + p;
        uh[br]         = __float2half(r0 - a * lr);
        uh[br + DHALF] = __float2half(i0 - a * li);
    }
}

// ---------- fused gist rotation + LN_gca (x1 fp16 in; x2h + a16 out) --------
__global__ void gist_rot_ln_kernel(const __half* __restrict__ x1h,
                                   const float* __restrict__ lw, const float* __restrict__ lb,
                                   const float* __restrict__ grw, const float* __restrict__ grb,
                                   const float* __restrict__ gc, const float* __restrict__ gs,
                                   const float* __restrict__ cw, const float* __restrict__ cb,
                                   __half* __restrict__ x2h,
                                   __half* __restrict__ a16) {
    int row = blockIdx.x;
    int b = row >> 11;
    const __half* p = x1h + (size_t)row * DMODEL;
    float xr[4], xi[4];
    #pragma unroll
    for (int jj = 0; jj < 4; jj++) {
        int q = threadIdx.x + 256 * jj;
        xr[jj] = __half2float(p[q]);
        xi[jj] = __half2float(p[q + DHALF]);
    }
    float s1 = 0.f;
    #pragma unroll
    for (int jj = 0; jj < 4; jj++) s1 += xr[jj] + xi[jj];
    float m1 = block_reduce_sum256(s1) * (1.f / DMODEL);
    float q1 = 0.f;
    #pragma unroll
    for (int jj = 0; jj < 4; jj++) {
        float dr = xr[jj] - m1, di = xi[jj] - m1;
        q1 += dr * dr + di * di;
    }
    float rstd1 = rsqrtf(block_reduce_sum256(q1) * (1.f / DMODEL) + 1e-5f);

    float xnr[4], xni[4], rr[4], ri[4];
    #pragma unroll
    for (int jj = 0; jj < 4; jj++) {
        int q = threadIdx.x + 256 * jj;
        xnr[jj] = (xr[jj] - m1) * rstd1 * lw[q] + lb[q];
        xni[jj] = (xi[jj] - m1) * rstd1 * lw[q + DHALF] + lb[q + DHALF];
        float c = gc[b * DHALF + q], sn = gs[b * DHALF + q];
        rr[jj] = xnr[jj] * c - xni[jj] * sn;
        ri[jj] = xnr[jj] * sn + xni[jj] * c;
    }
    float s2 = 0.f;
    #pragma unroll
    for (int jj = 0; jj < 4; jj++) s2 += rr[jj] + ri[jj];
    float m2 = block_reduce_sum256(s2) * (1.f / DMODEL);
    float q2 = 0.f;
    #pragma unroll
    for (int jj = 0; jj < 4; jj++) {
        float dr = rr[jj] - m2, di = ri[jj] - m2;
        q2 += dr * dr + di * di;
    }
    float rstd2 = rsqrtf(block_reduce_sum256(q2) * (1.f / DMODEL) + 1e-5f);

    float o_r[4], o_i[4];
    #pragma unroll
    for (int jj = 0; jj < 4; jj++) {
        int q = threadIdx.x + 256 * jj;
        o_r[jj] = xr[jj] + (rr[jj] - m2) * rstd2 * grw[q] + grb[q] - xnr[jj];
        o_i[jj] = xi[jj] + (ri[jj] - m2) * rstd2 * grw[q + DHALF] + grb[q + DHALF] - xni[jj];
    }

    float s3 = 0.f;
    #pragma unroll
    for (int jj = 0; jj < 4; jj++) s3 += o_r[jj] + o_i[jj];
    float m3 = block_reduce_sum256(s3) * (1.f / DMODEL);
    float q3 = 0.f;
    #pragma unroll
    for (int jj = 0; jj < 4; jj++) {
        float dr = o_r[jj] - m3, di = o_i[jj] - m3;
        q3 += dr * dr + di * di;
    }
    float rstd3 = rsqrtf(block_reduce_sum256(q3) * (1.f / DMODEL) + 1e-5f);

    #pragma unroll
    for (int jj = 0; jj < 4; jj++) {
        int q = threadIdx.x + 256 * jj;
        size_t ir = (size_t)row * DMODEL + q, ii = ir + DHALF;
        x2h[ir] = __float2half(o_r[jj]);
        x2h[ii] = __float2half(o_i[jj]);
        a16[ir] = __float2half((o_r[jj] - m3) * rstd3 * cw[q] + cb[q]);
        a16[ii] = __float2half((o_i[jj] - m3) * rstd3 * cw[q + DHALF] + cb[q + DHALF]);
    }
}

// ------------------- split-K small GEMMs (M=64) -----------------------------
#define SKC 64
__global__ __launch_bounds__(256, 4)
void smallgemm_kernel(const float* __restrict__ A, int lda,
                      const float* __restrict__ W, int ldw,
                      float* __restrict__ part, int Kdim) {
    __shared__ float Fs[64][SKC + 1];
    __shared__ float Ws[64][SKC + 1];
    const int n0 = blockIdx.x * 64;
    const int k0 = blockIdx.y * SKC;
    const int tid = threadIdx.x;

    for (int idx = tid; idx < 64 * SKC; idx += 256) {
        int r = idx >> 6, c = idx & 63;
        int k = k0 + c;
        Fs[r][c] = (k < Kdim) ? A[(size_t)r * lda + k] : 0.f;
        Ws[r][c] = (k < Kdim) ? W[(size_t)(n0 + r) * ldw + k] : 0.f;
    }
    __syncthreads();

    const int tx = tid & 15, ty = tid >> 4;
    float acc[4][4];
    #pragma unroll
    for (int i = 0; i < 4; i++)
        #pragma unroll
        for (int j = 0; j < 4; j++) acc[i][j] = 0.f;

    for (int k = 0; k < SKC; k++) {
        float ra[4], rb[4];
        #pragma unroll
        for (int i = 0; i < 4; i++) ra[i] = Fs[ty * 4 + i][k];
        #pragma unroll
        for (int j = 0; j < 4; j++) rb[j] = Ws[tx * 4 + j][k];
        #pragma unroll
        for (int i = 0; i < 4; i++)
            #pragma unroll
            for (int j = 0; j < 4; j++) acc[i][j] += ra[i] * rb[j];
    }

    float* pz = part + (size_t)blockIdx.y * (64 * DMODEL);
    #pragma unroll
    for (int i = 0; i < 4; i++)
        #pragma unroll
        for (int j = 0; j < 4; j++)
            pz[(size_t)(ty * 4 + i) * DMODEL + n0 + tx * 4 + j] = acc[i][j];
}

__global__ void skreduce_kernel(const float* __restrict__ part, int nparts,
                                const float* __restrict__ bias,
                                float* __restrict__ out) {
    int idx = blockIdx.x * 256 + threadIdx.x;
    if (idx >= 64 * DMODEL) return;
    float s = bias ? bias[idx & (DMODEL - 1)] : 0.f;
    for (int z = 0; z < nparts; z++) s += part[(size_t)z * (64 * DMODEL) + idx];
    out[idx] = s;
}

__global__ __launch_bounds__(256, 4)
void smallgemm_kv_kernel(const float* __restrict__ A,
                         const float* __restrict__ Wk,
                         const float* __restrict__ Wv,
                         float* __restrict__ part) {
    __shared__ float Fs[64][SKC + 1];
    __shared__ float Ws[64][SKC + 1];
    const int n0g = blockIdx.x * 64;
    const float* W = (n0g < DMODEL) ? Wk + (size_t)n0g * DMODEL
                                    : Wv + (size_t)(n0g - DMODEL) * DMODEL;
    const int k0 = blockIdx.y * SKC;
    const int tid = threadIdx.x;

    for (int idx = tid; idx < 64 * SKC; idx += 256) {
        int r = idx >> 6, c = idx & 63;
        Fs[r][c] = A[(size_t)r * DMODEL + k0 + c];
        Ws[r][c] = W[(size_t)r * DMODEL + k0 + c];
    }
    __syncthreads();

    const int tx = tid & 15, ty = tid >> 4;
    float acc[4][4];
    #pragma unroll
    for (int i = 0; i < 4; i++)
        #pragma unroll
        for (int j = 0; j < 4; j++) acc[i][j] = 0.f;

    for (int k = 0; k < SKC; k++) {
        float ra[4], rb[4];
        #pragma unroll
        for (int i = 0; i < 4; i++) ra[i] = Fs[ty * 4 + i][k];
        #pragma unroll
        for (int j = 0; j < 4; j++) rb[j] = Ws[tx * 4 + j][k];
        #pragma unroll
        for (int i = 0; i < 4; i++)
            #pragma unroll
            for (int j = 0; j < 4; j++) acc[i][j] += ra[i] * rb[j];
    }

    float* pz = part + (size_t)blockIdx.y * (64 * 2 * DMODEL);
    #pragma unroll
    for (int i = 0; i < 4; i++)
        #pragma unroll
        for (int j = 0; j < 4; j++)
            pz[(size_t)(ty * 4 + i) * (2 * DMODEL) + n0g + tx * 4 + j] = acc[i][j];
}

__global__ void skreduce_kv_kernel(const float* __restrict__ part, int nparts,
                                   float* __restrict__ kh, float* __restrict__ v) {
    int idx = blockIdx.x * 256 + threadIdx.x;
    if (idx >= 64 * 2 * DMODEL) return;
    float s = 0.f;
    for (int z = 0; z < nparts; z++) s += part[(size_t)z * (64 * 2 * DMODEL) + idx];
    int m = idx >> 12, n = idx & (2 * DMODEL - 1);
    if (n < DMODEL) kh[(size_t)m * DMODEL + n] = s;
    else            v [(size_t)m * DMODEL + (n - DMODEL)] = s;
}

// ------------------------- fp16 HMMA single-term GEMM -----------------------
#define GBK 64
#define ROWP 72
#define OFF_W     (128 * ROWP)
#define STAGE_EL  (384 * ROWP)
#define STAGE_B   (STAGE_EL * 2)
#define NSTAGE 3
#define SMEM_GEMM (NSTAGE * STAGE_B)           // 165888 bytes

__global__ __launch_bounds__(256, 1)
void gemm_f16_kernel(const __half* __restrict__ A16,
                     const __half* __restrict__ W16,
                     float* __restrict__ D,
                     __half* __restrict__ Dh,
                     const float* __restrict__ add1,
                     const __half* __restrict__ addh) {
    extern __shared__ __half sm[];
    const int tid  = threadIdx.x;
    const int lane = tid & 31;
    const int warp = tid >> 5;
    const int wm = warp & 1;
    const int wn = warp >> 1;
    const int m0 = blockIdx.y * 128, n0 = blockIdx.x * 256;
    const uint32_t smb = smem_u32(sm);

    float acc[4][8][4];
    #pragma unroll
    for (int mt = 0; mt < 4; mt++)
        #pragma unroll
        for (int nt = 0; nt < 8; nt++)
            #pragma unroll
            for (int j = 0; j < 4; j++) acc[mt][nt][j] = 0.f;

    const int NCHUNK = DMODEL / GBK;

    const int a_row = lane & 15;
    const int a_k8  = (lane >= 16) ? 8 : 0;
    const int b_row = (lane & 7) + ((lane >= 16) ? 8 : 0);
    const int b_k8  = ((lane >> 3) & 1) ? 8 : 0;

    auto issue_stage = [&](int kc, uint32_t sbase) {
        const int k0 = kc * GBK;
        #pragma unroll
        for (int i = 0; i < 4; i++) {
            int idx = tid + i * 256;
            int row = idx >> 3, ch = idx & 7;
            cpasync16(sbase + (uint32_t)(row * ROWP + ch * 8) * 2,
                      A16 + (size_t)(m0 + row) * DMODEL + k0 + ch * 8);
        }
        #pragma unroll
        for (int i = 0; i < 8; i++) {
            int idx = tid + i * 256;
            int row = idx >> 3, ch = idx & 7;
            cpasync16(sbase + (uint32_t)(OFF_W + row * ROWP + ch * 8) * 2,
                      W16 + (size_t)(n0 + row) * DMODEL + k0 + ch * 8);
        }
    };

    issue_stage(0, smb);
    CP_COMMIT();
    issue_stage(1, smb + STAGE_B);
    CP_COMMIT();

    for (int kc = 0; kc < NCHUNK; kc++) {
        if (kc + 2 < NCHUNK) {
            issue_stage(kc + 2, smb + ((kc + 2) % NSTAGE) * STAGE_B);
            CP_COMMIT();
            CP_WAIT(2);
        } else if (kc + 1 < NCHUNK) {
            CP_WAIT(1);
        } else {
            CP_WAIT(0);
        }
        __syncthreads();

        const uint32_t sbase = smb + (kc % NSTAGE) * STAGE_B;

        #pragma unroll
        for (int ks = 0; ks < 4; ks++) {
            const int kb = ks * 16;
            uint32_t ah[4][4];
            #pragma unroll
            for (int mt = 0; mt < 4; mt++) {
                int rowe = (wm * 64 + mt * 16 + a_row) * ROWP + kb + a_k8;
                ldsm_x4(ah[mt], sbase + (uint32_t)rowe * 2);
            }
            #pragma unroll
            for (int ntp = 0; ntp < 4; ntp++) {
                uint32_t bh[4];
                int rowe = OFF_W + (wn * 64 + ntp * 16 + b_row) * ROWP + kb + b_k8;
                ldsm_x4(bh, sbase + (uint32_t)rowe * 2);
                #pragma unroll
                for (int mt = 0; mt < 4; mt++) {
                    mma16816h(acc[mt][2 * ntp],     ah[mt], bh[0], bh[1]);
                    mma16816h(acc[mt][2 * ntp + 1], ah[mt], bh[2], bh[3]);
                }
            }
        }
        __syncthreads();
    }

    const int r  = lane >> 2;
    const int c2 = lane & 3;
    #pragma unroll
    for (int mt = 0; mt < 4; mt++) {
        #pragma unroll
        for (int nt = 0; nt < 8; nt++) {
            int row0 = m0 + wm * 64 + mt * 16 + r;
            int col  = n0 + wn * 64 + nt * 8 + c2 * 2;
            size_t i0 = (size_t)row0 * DMODEL + col;
            size_t i1 = i0 + (size_t)8 * DMODEL;
            float2 v0 = make_float2(acc[mt][nt][0], acc[mt][nt][1]);
            float2 v1 = make_float2(acc[mt][nt][2], acc[mt][nt][3]);
            if (add1) {
                float2 a0 = *(const float2*)(add1 + i0);
                float2 a1 = *(const float2*)(add1 + i1);
                v0.x += a0.x; v0.y += a0.y; v1.x += a1.x; v1.y += a1.y;
            }
            if (addh) {
                __half2 h0 = *(const __half2*)(addh + i0);
                __half2 h1 = *(const __half2*)(addh + i1);
                float2 f0 = __half22float2(h0), f1 = __half22float2(h1);
                v0.x += f0.x; v0.y += f0.y; v1.x += f1.x; v1.y += f1.y;
            }
            if (D) {
                *(float2*)(D + i0) = v0;
                *(float2*)(D + i1) = v1;
            }
            if (Dh) {
                *(__half2*)(Dh + i0) = __floats2half2_rn(v0.x, v0.y);
                *(__half2*)(Dh + i1) = __floats2half2_rn(v1.x, v1.y);
            }
        }
    }
}

// ------------------------- gist cross-attention (16 kv tokens) ---------------
__global__ void attn_kernel(const __half* __restrict__ Q,
                            const float* __restrict__ Kh,
                            const float* __restrict__ V,
                            __half* __restrict__ ch) {
    __shared__ float Ks[KGIST][HDIM];
    __shared__ float Vs[KGIST][HDIM];
    const int h = blockIdx.y, b = blockIdx.z;
    const int t0 = blockIdx.x * 32;
    for (int j = threadIdx.x; j < KGIST * HDIM; j += 256) {
        int k = j >> 7, c = j & 127;
        Ks[k][c] = Kh[(size_t)(b * KGIST + k) * DMODEL + h * HDIM + c];
        Vs[k][c] = V [(size_t)(b * KGIST + k) * DMODEL + h * HDIM + c];
    }
    __syncthreads();
    const int w = threadIdx.x >> 5, lane = threadIdx.x & 31;
    const float scale = 0.08838834764831845f;
    for (int it = 0; it < 4; it++) {
        int t = t0 + w * 4 + it;
        size_t base = ((size_t)(b * TLEN + t)) * DMODEL + h * HDIM + lane * 4;
        __half2 qh0 = *(const __half2*)(Q + base);
        __half2 qh1 = *(const __half2*)(Q + base + 2);
        float2 qf0 = __half22float2(qh0), qf1 = __half22float2(qh1);
        float q0 = qf0.x, q1 = qf0.y, q2 = qf1.x, q3 = qf1.y;
        float sc[KGIST];
        #pragma unroll
        for (int k = 0; k < KGIST; k++) {
            float ps = q0 * Ks[k][lane * 4] + q1 * Ks[k][lane * 4 + 1]
                     + q2 * Ks[k][lane * 4 + 2] + q3 * Ks[k][lane * 4 + 3];
            #pragma unroll
            for (int o = 16; o > 0; o >>= 1) ps += __shfl_xor_sync(0xffffffffu, ps, o);
            sc[k] = ps * scale;
        }
        float mx = sc[0];
        #pragma unroll
        for (int k = 1; k < KGIST; k++) mx = fmaxf(mx, sc[k]);
        float ssum = 0.f;
        #pragma unroll
        for (int k = 0; k < KGIST; k++) { sc[k] = expf(sc[k] - mx); ssum += sc[k]; }
        float inv = 1.f / ssum;
        float c0 = 0.f, c1 = 0.f, c2 = 0.f, c3 = 0.f;
        #pragma unroll
        for (int k = 0; k < KGIST; k++) {
            float wk = sc[k] * inv;
            c0 += wk * Vs[k][lane * 4];
            c1 += wk * Vs[k][lane * 4 + 1];
            c2 += wk * Vs[k][lane * 4 + 2];
            c3 += wk * Vs[k][lane * 4 + 3];
        }
        *(__half2*)(ch + base)     = __floats2half2_rn(c0, c1);
        *(__half2*)(ch + base + 2) = __floats2half2_rn(c2, c3);
    }
}

// ------------------------- launcher -----------------------------------------
extern "C" void kernel_launch(void* const* d_in, const int* in_sizes, int n_in,
                              void* d_out, int out_size) {
    const float* x             = (const float*)d_in[0];
    const float* gist_theta    = (const float*)d_in[1];
    const float* gist_mag      = (const float*)d_in[2];
    const float* gist_weights  = (const float*)d_in[3];
    const float* ln_sheaf_w    = (const float*)d_in[4];
    const float* ln_sheaf_b    = (const float*)d_in[5];
    const float* sheaf_thetas  = (const float*)d_in[6];
    const float* alpha         = (const float*)d_in[7];
    const float* corr_W        = (const float*)d_in[8];
    const float* ln_gist_w     = (const float*)d_in[9];
    const float* ln_gist_b     = (const float*)d_in[10];
    const float* gist_strength = (const float*)d_in[11];
    const float* gr_ln_w       = (const float*)d_in[12];
    const float* gr_ln_b       = (const float*)d_in[13];
    const float* ln_gca_w      = (const float*)d_in[14];
    const float* ln_gca_b      = (const float*)d_in[15];
    const float* Wq            = (const float*)d_in[16];
    const float* Wk            = (const float*)d_in[17];
    const float* Wv            = (const float*)d_in[18];
    const float* Wo            = (const float*)d_in[19];
    const float* gist_up_W     = (const float*)d_in[20];
    const float* gist_up_b     = (const float*)d_in[21];
    float* out = (float*)d_out;

    float *feat, *part, *repr, *kh, *v, *shc, *shs, *gc, *gs;
    float2* stats;
    __half *x1h, *x2h, *a16, *q16, *w16a, *w16b, *w16c;
    cudaGetSymbolAddress((void**)&x1h,  g_x1h);
    cudaGetSymbolAddress((void**)&x2h,  g_x2h);
    cudaGetSymbolAddress((void**)&a16,  g_a16);
    cudaGetSymbolAddress((void**)&q16,  g_q16);
    cudaGetSymbolAddress((void**)&w16a, g_w16a);
    cudaGetSymbolAddress((void**)&w16b, g_w16b);
    cudaGetSymbolAddress((void**)&w16c, g_w16c);
    cudaGetSymbolAddress((void**)&stats, g_stats);
    cudaGetSymbolAddress((void**)&feat, g_feat);
    cudaGetSymbolAddress((void**)&part, g_part);
    cudaGetSymbolAddress((void**)&repr, g_repr);
    cudaGetSymbolAddress((void**)&kh,   g_kh);
    cudaGetSymbolAddress((void**)&v,    g_v);
    cudaGetSymbolAddress((void**)&shc,  g_shc);
    cudaGetSymbolAddress((void**)&shs,  g_shs);
    cudaGetSymbolAddress((void**)&gc,   g_gc);
    cudaGetSymbolAddress((void**)&gs,   g_gs);

    cudaFuncSetAttribute(gemm_f16_kernel,
                         cudaFuncAttributeMaxDynamicSharedMemorySize, SMEM_GEMM);

    dim3 ggemm(DMODEL / 256, NROWS / 128);   // (8, 64)
    const int wsplit4 = DMODEL * DMODEL / 4;
    const int kp_up = (KUP + SKC - 1) / SKC;       // 17
    const int kp_d  = DMODEL / SKC;                // 32
    const int redgrid   = (64 * DMODEL + 255) / 256;
    const int redgridkv = (64 * 2 * DMODEL + 255) / 256;

    // side stream (forked from the capture/default stream via events)
    cudaStream_t s2;
    cudaStreamCreateWithFlags(&s2, cudaStreamNonBlocking);
    cudaEvent_t evFork, evW, evChain;
    cudaEventCreateWithFlags(&evFork,  cudaEventDisableTiming);
    cudaEventCreateWithFlags(&evW,     cudaEventDisableTiming);
    cudaEventCreateWithFlags(&evChain, cudaEventDisableTiming);

    // prep (main stream)
    prep_sheaf_cs_kernel<<<16, 256>>>(sheaf_thetas, shc, shs);
    gist_theta_kernel<<<BATCH, 256>>>(gist_theta, gist_mag, gist_weights, gist_strength, gc, gs);
    feat_kernel<<<BATCH * KGIST, 256>>>(gist_theta, gist_mag, feat);

    // fork side stream
    cudaEventRecord(evFork, 0);
    cudaStreamWaitEvent(s2, evFork, 0);

    // s2: weight conversions + gist K/V chain (independent of stage 1/2)
    w16_kernel<<<(wsplit4 + 255) / 256, 256, 0, s2>>>(corr_W, w16a, wsplit4);
    w16_kernel<<<(wsplit4 + 255) / 256, 256, 0, s2>>>(Wq,     w16b, wsplit4);
    w16_kernel<<<(wsplit4 + 255) / 256, 256, 0, s2>>>(Wo,     w16c, wsplit4);
    cudaEventRecord(evW, s2);
    smallgemm_kernel<<<dim3(32, kp_up), 256, 0, s2>>>(feat, KUP, gist_up_W, KUP, part, KUP);
    skreduce_kernel<<<redgrid, 256, 0, s2>>>(part, kp_up, gist_up_b, repr);
    smallgemm_kv_kernel<<<dim3(64, kp_d), 256, 0, s2>>>(repr, Wk, Wv, part);
    skreduce_kv_kernel<<<redgridkv, 256, 0, s2>>>(part, kp_d, kh, v);
    cudaEventRecord(evChain, s2);

    // main: stage 1 (sheaf residual)
    rowstats_kernel<<<NROWS, 256>>>(x, stats);
    sheaf_apply_kernel<<<NROWS, 256>>>(x, ln_sheaf_w, ln_sheaf_b, shc, shs, alpha, stats, a16);
    cudaStreamWaitEvent(0, evW, 0);           // weights ready
    gemm_f16_kernel<<<ggemm, 256, SMEM_GEMM>>>(a16, w16a, nullptr, x1h, x, a16);

    // stage 2: gist rotation + LN_gca (fused)
    gist_rot_ln_kernel<<<NROWS, 256>>>(x1h, ln_gist_w, ln_gist_b, gr_ln_w, gr_ln_b,
                                       gc, gs, ln_gca_w, ln_gca_b, x2h, a16);

    // stage 3: cross-attention residual
    gemm_f16_kernel<<<ggemm, 256, SMEM_GEMM>>>(a16, w16b, nullptr, q16, nullptr, nullptr);
    cudaStreamWaitEvent(0, evChain, 0);       // kh, v ready
    attn_kernel<<<dim3(TLEN / 32, NHEADS, BATCH), 256>>>(q16, kh, v, a16);
    gemm_f16_kernel<<<ggemm, 256, SMEM_GEMM>>>(a16, w16c, out, nullptr, nullptr, x2h);

    cudaEventDestroy(evFork);
    cudaEventDestroy(evW);
    cudaEventDestroy(evChain);
    cudaStreamDestroy(s2);

    (void)in_sizes; (void)n_in; (void)out_size;
}